// round 1
// baseline (speedup 1.0000x reference)
#include <cuda_runtime.h>
#include <float.h>
#include <math.h>

// Problem constants (fixed shapes for this bench)
#define BB   4
#define LL   1024
#define DIMM 1024
#define HH   16
#define DHH  64
#define FF   32      // DH/2 rope frequencies
#define NC   2       // NUM_CHAINS
#define TWO_PI_F 6.2831853071795864769f

// ---------------- scratch (static device globals; no allocation) -----------
__device__ float g_st[BB * DIMM];                 // silu(time)
__device__ float g_ss[BB * 2 * DIMM];             // scale|shift per batch
__device__ float g_counts[BB * NC];               // cyclic counts per chain
__device__ float g_xc[(size_t)BB * LL * DIMM];    // modulated LN output
__device__ float g_qt[(size_t)BB * LL * HH * DHH];     // q pre-rope [BL,1024]
__device__ float g_kvt[(size_t)BB * LL * 2 * HH * DHH];// kv pre-rope [BL,2048]
__device__ float g_q[(size_t)BB * HH * LL * DHH]; // [B,H,L,DH] rope'd, *DH^-0.5
__device__ float g_k[(size_t)BB * HH * LL * DHH];
__device__ float g_v[(size_t)BB * HH * LL * DHH];
__device__ float g_ao[(size_t)BB * LL * HH * DHH];// attention out [B,L,H*DH]

// ---------------- 1. silu(time) --------------------------------------------
__global__ void silu_k(const float* __restrict__ timep) {
    int i = blockIdx.x * 256 + threadIdx.x;
    if (i < BB * DIMM) {
        float t = timep[i];
        g_st[i] = t / (1.0f + expf(-t));
    }
}

// ---------------- 2. cyclic counts ------------------------------------------
__global__ void zero_counts_k() {
    if (threadIdx.x < BB * NC) g_counts[threadIdx.x] = 0.0f;
}
__global__ void count_k(const int* __restrict__ chain_index,
                        const float* __restrict__ cyclic_mask) {
    int i = blockIdx.x * 256 + threadIdx.x;
    if (i < BB * LL) {
        int b = i / LL;
        atomicAdd(&g_counts[b * NC + chain_index[i]], cyclic_mask[i]);
    }
}

// ---------------- 3. ss = silu(time) @ Wt^T + bt ----------------------------
__global__ void ss_gemv_k(const float* __restrict__ Wt,
                          const float* __restrict__ bt) {
    int warp = (blockIdx.x * blockDim.x + threadIdx.x) >> 5;
    int lane = threadIdx.x & 31;
    if (warp >= BB * 2 * DIMM) return;
    int b = warp / (2 * DIMM);
    int r = warp % (2 * DIMM);
    const float4* w4 = (const float4*)(Wt + (size_t)r * DIMM);
    const float4* s4 = (const float4*)(g_st + b * DIMM);
    float sum = 0.0f;
#pragma unroll
    for (int i = 0; i < 8; i++) {
        float4 w = w4[lane + i * 32];
        float4 s = s4[lane + i * 32];
        sum += w.x * s.x + w.y * s.y + w.z * s.z + w.w * s.w;
    }
#pragma unroll
    for (int o = 16; o; o >>= 1) sum += __shfl_down_sync(0xffffffffu, sum, o);
    if (lane == 0) g_ss[b * 2 * DIMM + r] = sum + bt[r];
}

// ---------------- 4. LayerNorm + (scale+1)*xn + shift ------------------------
__global__ void ln_mod_k(const float* __restrict__ x,
                         const float* __restrict__ seq_mask,
                         const float* __restrict__ gamma) {
    int row = blockIdx.x;          // b*L + l
    int b   = row / LL;
    int tid = threadIdx.x;

    float mval = seq_mask[row];
    float4 xv = ((const float4*)x)[(size_t)row * 256 + tid];
    xv.x *= mval; xv.y *= mval; xv.z *= mval; xv.w *= mval;

    float s = xv.x + xv.y + xv.z + xv.w;
    float q = xv.x * xv.x + xv.y * xv.y + xv.z * xv.z + xv.w * xv.w;

    __shared__ float rs[256];
    __shared__ float rq[256];
    rs[tid] = s; rq[tid] = q;
    __syncthreads();
#pragma unroll
    for (int o = 128; o; o >>= 1) {
        if (tid < o) { rs[tid] += rs[tid + o]; rq[tid] += rq[tid + o]; }
        __syncthreads();
    }
    float mu   = rs[0] * (1.0f / DIMM);
    float var  = rq[0] * (1.0f / DIMM) - mu * mu;
    float rstd = rsqrtf(var + 1e-5f);

    float4 g  = ((const float4*)gamma)[tid];
    float4 sc = ((const float4*)g_ss)[b * 512 + tid];
    float4 sh = ((const float4*)g_ss)[b * 512 + 256 + tid];

    float4 o;
    o.x = (xv.x - mu) * rstd * g.x * (sc.x + 1.0f) + sh.x;
    o.y = (xv.y - mu) * rstd * g.y * (sc.y + 1.0f) + sh.y;
    o.z = (xv.z - mu) * rstd * g.z * (sc.z + 1.0f) + sh.z;
    o.w = (xv.w - mu) * rstd * g.w * (sc.w + 1.0f) + sh.w;
    ((float4*)g_xc)[(size_t)row * 256 + tid] = o;
}

// ---------------- 5. SGEMM: C[M,N] = A[M,K] * W[N,K]^T  (opt row mask) ------
__global__ __launch_bounds__(256)
void sgemm_k(const float* __restrict__ A, const float* __restrict__ W,
             float* __restrict__ C, int M, int N, int K,
             const float* __restrict__ rowmask) {
    const int BM = 128, BN = 128, BK = 8;
    __shared__ float As[BK][BM];
    __shared__ float Bs[BK][BN];
    int tid = threadIdx.x;
    int m0 = blockIdx.y * BM;
    int n0 = blockIdx.x * BN;
    int ty = tid >> 4, tx = tid & 15;

    float acc[8][8] = {};

    int aRow = tid >> 1;
    int aK4  = (tid & 1) * 4;

    for (int k0 = 0; k0 < K; k0 += BK) {
        float4 av = *(const float4*)&A[(size_t)(m0 + aRow) * K + k0 + aK4];
        float4 bv = *(const float4*)&W[(size_t)(n0 + aRow) * K + k0 + aK4];
        As[aK4 + 0][aRow] = av.x; As[aK4 + 1][aRow] = av.y;
        As[aK4 + 2][aRow] = av.z; As[aK4 + 3][aRow] = av.w;
        Bs[aK4 + 0][aRow] = bv.x; Bs[aK4 + 1][aRow] = bv.y;
        Bs[aK4 + 2][aRow] = bv.z; Bs[aK4 + 3][aRow] = bv.w;
        __syncthreads();
#pragma unroll
        for (int kk = 0; kk < BK; kk++) {
            float a[8], bvals[8];
            *(float4*)&a[0]     = *(const float4*)&As[kk][ty * 8];
            *(float4*)&a[4]     = *(const float4*)&As[kk][ty * 8 + 4];
            *(float4*)&bvals[0] = *(const float4*)&Bs[kk][tx * 8];
            *(float4*)&bvals[4] = *(const float4*)&Bs[kk][tx * 8 + 4];
#pragma unroll
            for (int i = 0; i < 8; i++)
#pragma unroll
                for (int j = 0; j < 8; j++)
                    acc[i][j] += a[i] * bvals[j];
        }
        __syncthreads();
    }

#pragma unroll
    for (int i = 0; i < 8; i++) {
        int m = m0 + ty * 8 + i;
        float mm = rowmask ? rowmask[m] : 1.0f;
        float4 v0, v1;
        v0.x = acc[i][0] * mm; v0.y = acc[i][1] * mm;
        v0.z = acc[i][2] * mm; v0.w = acc[i][3] * mm;
        v1.x = acc[i][4] * mm; v1.y = acc[i][5] * mm;
        v1.z = acc[i][6] * mm; v1.w = acc[i][7] * mm;
        *(float4*)&C[(size_t)m * N + n0 + tx * 8]     = v0;
        *(float4*)&C[(size_t)m * N + n0 + tx * 8 + 4] = v1;
    }
}

// ---------------- 6. cyclic RoPE + transpose to [B,H,L,DH] ------------------
__global__ void rope_k(const float* __restrict__ rope_freqs,
                       const int* __restrict__ residue_index,
                       const int* __restrict__ chain_index,
                       const float* __restrict__ cyclic_mask) {
    int row = blockIdx.x;          // b*L + l
    int b = row / LL, l = row % LL;
    int tid = threadIdx.x;

    __shared__ float cs[FF], sn[FF];
    if (tid < FF) {
        float t  = (float)residue_index[row];
        int   ci = chain_index[row];
        float cm = cyclic_mask[row];
        float a;
        if (cm > 0.0f) {
            float ring = g_counts[b * NC + ci] * cm;
            float rsafe = fmaxf(ring, 1.0f);
            float mk = fmaxf(floorf(rsafe * 0.5f), 1.0f);
            float kf = (float)(tid + 1);
            float keff = (mk == 1.0f) ? 1.0f : (1.0f + fmodf(kf - 1.0f, mk));
            float om = (TWO_PI_F * keff) / rsafe;
            a = om * t;
        } else {
            a = t * rope_freqs[tid] + (float)ci * rope_freqs[0];
        }
        sincosf(a, &sn[tid], &cs[tid]);
    }
    __syncthreads();

    const float2* q2 = (const float2*)(g_qt  + (size_t)row * 1024);
    const float2* k2 = (const float2*)(g_kvt + (size_t)row * 2048);
    const float2* v2 = (const float2*)(g_kvt + (size_t)row * 2048 + 1024);

#pragma unroll
    for (int i = 0; i < 4; i++) {
        int p = tid + i * 128;       // 0..511: pair index; h = p/32, f = p%32
        int h = p >> 5, f = p & 31;
        float c = cs[f], s = sn[f];
        float2 q = q2[p];
        float2 k = k2[p];
        float2 v = v2[p];
        size_t dst = ((size_t)(b * HH + h) * LL + l) * 32 + f;   // float2 idx
        ((float2*)g_q)[dst] = make_float2((q.x * c - q.y * s) * 0.125f,
                                          (q.y * c + q.x * s) * 0.125f);
        ((float2*)g_k)[dst] = make_float2(k.x * c - k.y * s,
                                          k.y * c + k.x * s);
        ((float2*)g_v)[dst] = v;
    }
}

// ---------------- 7. attention (flash-style, one query row per thread) ------
__global__ __launch_bounds__(64)
void attn_k(const float* __restrict__ seq_mask) {
    __shared__ float4 Ks[64 * 16];
    __shared__ float4 Vs[64 * 16];
    __shared__ float  km[64];

    int b = blockIdx.z, h = blockIdx.y, qt = blockIdx.x;
    int tid = threadIdx.x;
    size_t bh = (size_t)(b * HH + h);

    const float4* q4 = (const float4*)g_q + (bh * LL + qt * 64 + tid) * 16;
    float4 qf[16];
#pragma unroll
    for (int i = 0; i < 16; i++) qf[i] = q4[i];

    float4 of[16];
#pragma unroll
    for (int i = 0; i < 16; i++) of[i] = make_float4(0.f, 0.f, 0.f, 0.f);
    float m = -FLT_MAX, lsum = 0.0f;

    for (int kt = 0; kt < 16; kt++) {
        const float4* kk4 = (const float4*)g_k + (bh * LL + kt * 64) * 16;
        const float4* vv4 = (const float4*)g_v + (bh * LL + kt * 64) * 16;
#pragma unroll
        for (int i = 0; i < 16; i++) {
            Ks[tid + i * 64] = kk4[tid + i * 64];
            Vs[tid + i * 64] = vv4[tid + i * 64];
        }
        km[tid] = seq_mask[b * LL + kt * 64 + tid];
        __syncthreads();

        float sv[64];
        float tm = -FLT_MAX;
#pragma unroll
        for (int j = 0; j < 64; j++) {
            float s = 0.0f;
            const float4* kr = &Ks[j * 16];
#pragma unroll
            for (int d = 0; d < 16; d++) {
                float4 kv = kr[d];
                s += qf[d].x * kv.x + qf[d].y * kv.y +
                     qf[d].z * kv.z + qf[d].w * kv.w;
            }
            s = (km[j] > 0.0f) ? s : -FLT_MAX;
            sv[j] = s;
            tm = fmaxf(tm, s);
        }

        float mnew = fmaxf(m, tm);
        float corr = __expf(m - mnew);
        lsum *= corr;
#pragma unroll
        for (int d = 0; d < 16; d++) {
            of[d].x *= corr; of[d].y *= corr; of[d].z *= corr; of[d].w *= corr;
        }
#pragma unroll
        for (int j = 0; j < 64; j++) {
            float p = __expf(sv[j] - mnew);
            lsum += p;
            const float4* vr = &Vs[j * 16];
#pragma unroll
            for (int d = 0; d < 16; d++) {
                float4 vv = vr[d];
                of[d].x += p * vv.x; of[d].y += p * vv.y;
                of[d].z += p * vv.z; of[d].w += p * vv.w;
            }
        }
        m = mnew;
        __syncthreads();
    }

    float inv = 1.0f / lsum;
    float4* o4 = (float4*)g_ao + ((size_t)b * LL + qt * 64 + tid) * 256 + h * 16;
#pragma unroll
    for (int d = 0; d < 16; d++) {
        float4 v = of[d];
        v.x *= inv; v.y *= inv; v.z *= inv; v.w *= inv;
        o4[d] = v;
    }
}

// ---------------- launch ----------------------------------------------------
extern "C" void kernel_launch(void* const* d_in, const int* in_sizes, int n_in,
                              void* d_out, int out_size) {
    const float* x           = (const float*)d_in[0];
    const float* timep       = (const float*)d_in[1];
    const float* seq_mask    = (const float*)d_in[2];
    const float* cyclic_mask = (const float*)d_in[3];
    const float* gamma       = (const float*)d_in[4];
    const float* Wt          = (const float*)d_in[5];
    const float* bt          = (const float*)d_in[6];
    const float* Wq          = (const float*)d_in[7];
    const float* Wkv         = (const float*)d_in[8];
    const float* Wo          = (const float*)d_in[9];
    const float* rope_freqs  = (const float*)d_in[10];
    const int*   residue_idx = (const int*)d_in[11];
    const int*   chain_idx   = (const int*)d_in[12];
    float* out = (float*)d_out;

    float *xc, *qt, *kvt, *ao;
    cudaGetSymbolAddress((void**)&xc,  g_xc);
    cudaGetSymbolAddress((void**)&qt,  g_qt);
    cudaGetSymbolAddress((void**)&kvt, g_kvt);
    cudaGetSymbolAddress((void**)&ao,  g_ao);

    silu_k<<<16, 256>>>(timep);
    zero_counts_k<<<1, 32>>>();
    count_k<<<16, 256>>>(chain_idx, cyclic_mask);
    ss_gemv_k<<<1024, 256>>>(Wt, bt);
    ln_mod_k<<<BB * LL, 256>>>(x, seq_mask, gamma);

    // q = xc @ Wq^T  : [4096,1024]
    sgemm_k<<<dim3(DIMM / 128, (BB * LL) / 128), 256>>>(
        xc, Wq, qt, BB * LL, HH * DHH, DIMM, nullptr);
    // kv = xc @ Wkv^T : [4096,2048]
    sgemm_k<<<dim3((2 * DIMM) / 128, (BB * LL) / 128), 256>>>(
        xc, Wkv, kvt, BB * LL, 2 * HH * DHH, DIMM, nullptr);

    rope_k<<<BB * LL, 128>>>(rope_freqs, residue_idx, chain_idx, cyclic_mask);

    attn_k<<<dim3(LL / 64, HH, BB), 64>>>(seq_mask);

    // out = ao @ Wo^T, masked
    sgemm_k<<<dim3(DIMM / 128, (BB * LL) / 128), 256>>>(
        ao, Wo, out, BB * LL, DIMM, HH * DHH, seq_mask);
}

// round 3
// speedup vs baseline: 1.3757x; 1.3757x over previous
#include <cuda_runtime.h>
#include <cuda_bf16.h>
#include <float.h>
#include <math.h>
#include <stdint.h>

// Problem constants (fixed shapes for this bench)
#define BB   4
#define LL   1024
#define DIMM 1024
#define HH   16
#define DHH  64
#define FF   32      // DH/2 rope frequencies
#define NC   2       // NUM_CHAINS
#define TWO_PI_F 6.2831853071795864769f

// ---------------- scratch (static device globals; no allocation) -----------
__device__ float g_st[BB * DIMM];                 // silu(time)
__device__ float g_ss[BB * 2 * DIMM];             // scale|shift per batch
__device__ float g_counts[BB * NC];               // cyclic counts per chain

// split-bf16 operands
__device__ __nv_bfloat16 g_xh[(size_t)BB * LL * DIMM];   // LN+mod output hi
__device__ __nv_bfloat16 g_xl[(size_t)BB * LL * DIMM];   // LN+mod output lo
__device__ __nv_bfloat16 g_wh[(size_t)3 * DIMM * DIMM];  // [Wq;Wkv] hi (3072x1024)
__device__ __nv_bfloat16 g_wl[(size_t)3 * DIMM * DIMM];  // [Wq;Wkv] lo
__device__ __nv_bfloat16 g_woh[(size_t)DIMM * DIMM];     // Wo hi
__device__ __nv_bfloat16 g_wol[(size_t)DIMM * DIMM];     // Wo lo
__device__ __nv_bfloat16 g_aoh[(size_t)BB * LL * DIMM];  // attn out hi
__device__ __nv_bfloat16 g_aol[(size_t)BB * LL * DIMM];  // attn out lo

__device__ float g_qkv[(size_t)BB * LL * 3 * DIMM];      // fused q|k|v GEMM out
__device__ float g_q[(size_t)BB * HH * LL * DHH]; // [B,H,L,DH] rope'd, *DH^-0.5
__device__ float g_k[(size_t)BB * HH * LL * DHH];
__device__ float g_v[(size_t)BB * HH * LL * DHH];

// ============================================================================
// PTX helpers (base ISA only — sm_80+ instructions, no 'a'-features)
// ============================================================================
__device__ __forceinline__ uint32_t smem_u32(const void* p) {
    uint32_t a;
    asm("{ .reg .u64 t; cvta.to.shared.u64 t, %1; cvt.u32.u64 %0, t; }"
        : "=r"(a) : "l"(p));
    return a;
}
__device__ __forceinline__ void cpa16(uint32_t dst, const void* src) {
    asm volatile("cp.async.cg.shared.global [%0], [%1], 16;"
                 :: "r"(dst), "l"(src) : "memory");
}
#define CP_COMMIT() asm volatile("cp.async.commit_group;" ::: "memory")
#define CP_WAIT(N)  asm volatile("cp.async.wait_group %0;" :: "n"(N) : "memory")

__device__ __forceinline__ void mma16816(float* d, const uint32_t* a,
                                         const uint32_t* b) {
    asm volatile(
        "mma.sync.aligned.m16n8k16.row.col.f32.bf16.bf16.f32 "
        "{%0,%1,%2,%3}, {%4,%5,%6,%7}, {%8,%9}, {%0,%1,%2,%3};"
        : "+f"(d[0]), "+f"(d[1]), "+f"(d[2]), "+f"(d[3])
        : "r"(a[0]), "r"(a[1]), "r"(a[2]), "r"(a[3]), "r"(b[0]), "r"(b[1]));
}

// ---------------- 1. silu(time) --------------------------------------------
__global__ void silu_k(const float* __restrict__ timep) {
    int i = blockIdx.x * 256 + threadIdx.x;
    if (i < BB * DIMM) {
        float t = timep[i];
        g_st[i] = t / (1.0f + expf(-t));
    }
}

// ---------------- 2. cyclic counts ------------------------------------------
__global__ void zero_counts_k() {
    if (threadIdx.x < BB * NC) g_counts[threadIdx.x] = 0.0f;
}
__global__ void count_k(const int* __restrict__ chain_index,
                        const float* __restrict__ cyclic_mask) {
    int i = blockIdx.x * 256 + threadIdx.x;
    if (i < BB * LL) {
        int b = i / LL;
        atomicAdd(&g_counts[b * NC + chain_index[i]], cyclic_mask[i]);
    }
}

// ---------------- 3. ss = silu(time) @ Wt^T + bt ----------------------------
__global__ void ss_gemv_k(const float* __restrict__ Wt,
                          const float* __restrict__ bt) {
    int warp = (blockIdx.x * blockDim.x + threadIdx.x) >> 5;
    int lane = threadIdx.x & 31;
    if (warp >= BB * 2 * DIMM) return;
    int b = warp / (2 * DIMM);
    int r = warp % (2 * DIMM);
    const float4* w4 = (const float4*)(Wt + (size_t)r * DIMM);
    const float4* s4 = (const float4*)(g_st + b * DIMM);
    float sum = 0.0f;
#pragma unroll
    for (int i = 0; i < 8; i++) {
        float4 w = w4[lane + i * 32];
        float4 s = s4[lane + i * 32];
        sum += w.x * s.x + w.y * s.y + w.z * s.z + w.w * s.w;
    }
#pragma unroll
    for (int o = 16; o; o >>= 1) sum += __shfl_down_sync(0xffffffffu, sum, o);
    if (lane == 0) g_ss[b * 2 * DIMM + r] = sum + bt[r];
}

// ---------------- 4. fp32 -> split bf16 conversion ---------------------------
__global__ void split_k(const float* __restrict__ src,
                        __nv_bfloat16* __restrict__ hi,
                        __nv_bfloat16* __restrict__ lo, int n4) {
    int i = blockIdx.x * 256 + threadIdx.x;
    if (i < n4) {
        float4 x = ((const float4*)src)[i];
        __nv_bfloat16 hx = __float2bfloat16(x.x);
        __nv_bfloat16 hy = __float2bfloat16(x.y);
        __nv_bfloat16 hz = __float2bfloat16(x.z);
        __nv_bfloat16 hw = __float2bfloat16(x.w);
        __nv_bfloat162 h01, h23, l01, l23;
        h01.x = hx; h01.y = hy; h23.x = hz; h23.y = hw;
        l01.x = __float2bfloat16(x.x - __bfloat162float(hx));
        l01.y = __float2bfloat16(x.y - __bfloat162float(hy));
        l23.x = __float2bfloat16(x.z - __bfloat162float(hz));
        l23.y = __float2bfloat16(x.w - __bfloat162float(hw));
        ((__nv_bfloat162*)hi)[i * 2]     = h01;
        ((__nv_bfloat162*)hi)[i * 2 + 1] = h23;
        ((__nv_bfloat162*)lo)[i * 2]     = l01;
        ((__nv_bfloat162*)lo)[i * 2 + 1] = l23;
    }
}

// ---------------- 5. LayerNorm + modulation (writes split bf16) --------------
__global__ void ln_mod_k(const float* __restrict__ x,
                         const float* __restrict__ seq_mask,
                         const float* __restrict__ gamma) {
    int row = blockIdx.x;          // b*L + l
    int b   = row / LL;
    int tid = threadIdx.x;

    float mval = seq_mask[row];
    float4 xv = ((const float4*)x)[(size_t)row * 256 + tid];
    xv.x *= mval; xv.y *= mval; xv.z *= mval; xv.w *= mval;

    float s = xv.x + xv.y + xv.z + xv.w;
    float q = xv.x * xv.x + xv.y * xv.y + xv.z * xv.z + xv.w * xv.w;

    __shared__ float rs[256];
    __shared__ float rq[256];
    rs[tid] = s; rq[tid] = q;
    __syncthreads();
#pragma unroll
    for (int o = 128; o; o >>= 1) {
        if (tid < o) { rs[tid] += rs[tid + o]; rq[tid] += rq[tid + o]; }
        __syncthreads();
    }
    float mu   = rs[0] * (1.0f / DIMM);
    float var  = rq[0] * (1.0f / DIMM) - mu * mu;
    float rstd = rsqrtf(var + 1e-5f);

    float4 g  = ((const float4*)gamma)[tid];
    float4 sc = ((const float4*)g_ss)[b * 512 + tid];
    float4 sh = ((const float4*)g_ss)[b * 512 + 256 + tid];

    float4 o;
    o.x = (xv.x - mu) * rstd * g.x * (sc.x + 1.0f) + sh.x;
    o.y = (xv.y - mu) * rstd * g.y * (sc.y + 1.0f) + sh.y;
    o.z = (xv.z - mu) * rstd * g.z * (sc.z + 1.0f) + sh.z;
    o.w = (xv.w - mu) * rstd * g.w * (sc.w + 1.0f) + sh.w;

    __nv_bfloat16 hx = __float2bfloat16(o.x);
    __nv_bfloat16 hy = __float2bfloat16(o.y);
    __nv_bfloat16 hz = __float2bfloat16(o.z);
    __nv_bfloat16 hw = __float2bfloat16(o.w);
    __nv_bfloat162 h01, h23, l01, l23;
    h01.x = hx; h01.y = hy; h23.x = hz; h23.y = hw;
    l01.x = __float2bfloat16(o.x - __bfloat162float(hx));
    l01.y = __float2bfloat16(o.y - __bfloat162float(hy));
    l23.x = __float2bfloat16(o.z - __bfloat162float(hz));
    l23.y = __float2bfloat16(o.w - __bfloat162float(hw));
    size_t p = (size_t)row * 512 + tid * 2;
    ((__nv_bfloat162*)g_xh)[p]     = h01;
    ((__nv_bfloat162*)g_xh)[p + 1] = h23;
    ((__nv_bfloat162*)g_xl)[p]     = l01;
    ((__nv_bfloat162*)g_xl)[p + 1] = l23;
}

// ---------------- 6. mma.sync split-bf16 GEMM: C = A @ B^T -------------------
// A[M,K], B[N,K] hi/lo bf16 row-major. Block tile 128x128, BK=32, 8 warps
// (2x4), warptile 64x32. 3 products: Ah*Bh + Ah*Bl + Al*Bh.
// SMEM tile: 128 rows x 32 k, stride 40 bf16 (80B) -> conflict-free frag loads.
#define TILE_B   10240                       // bytes per tile (128*40*2)
#define STAGE_B  (4 * TILE_B)                // Ah,Al,Bh,Bl
#define SM_TOT   (2 * STAGE_B)               // double buffered: 81920 B

__global__ __launch_bounds__(256)
void mma_gemm_k(const __nv_bfloat16* __restrict__ Ah,
                const __nv_bfloat16* __restrict__ Al,
                const __nv_bfloat16* __restrict__ Bh,
                const __nv_bfloat16* __restrict__ Bl,
                float* __restrict__ C, int K, int ldc,
                const float* __restrict__ rowmask) {
    extern __shared__ __align__(16) char smem[];
    const int tid  = threadIdx.x;
    const int wid  = tid >> 5;
    const int lane = tid & 31;
    const int gid  = lane >> 2;          // 0..7
    const int tig  = lane & 3;           // 0..3
    const int m0 = blockIdx.y * 128;
    const int n0 = blockIdx.x * 128;
    const int wm = wid & 1;              // 0..1  (m warp)
    const int wn = wid >> 1;             // 0..3  (n warp)

    uint32_t sb = smem_u32(smem);

    // gmem load mapping: row = tid>>1, 16 consecutive k elems at (tid&1)*16
    const int lrow = tid >> 1;
    const int lk   = (tid & 1) * 16;
    const __nv_bfloat16* gAh = Ah + (size_t)(m0 + lrow) * K + lk;
    const __nv_bfloat16* gAl = Al + (size_t)(m0 + lrow) * K + lk;
    const __nv_bfloat16* gBh = Bh + (size_t)(n0 + lrow) * K + lk;
    const __nv_bfloat16* gBl = Bl + (size_t)(n0 + lrow) * K + lk;
    const uint32_t doff = (uint32_t)lrow * 80 + (uint32_t)lk * 2;

    float acc[4][4][4];
#pragma unroll
    for (int a = 0; a < 4; a++)
#pragma unroll
        for (int b = 0; b < 4; b++)
#pragma unroll
            for (int c = 0; c < 4; c++) acc[a][b][c] = 0.0f;

    const int niter = K >> 5;

    // prologue: stage 0
    {
        uint32_t base = sb;
        cpa16(base + doff,                 gAh);
        cpa16(base + doff + 16,            gAh + 8);
        cpa16(base + TILE_B + doff,        gAl);
        cpa16(base + TILE_B + doff + 16,   gAl + 8);
        cpa16(base + 2 * TILE_B + doff,      gBh);
        cpa16(base + 2 * TILE_B + doff + 16, gBh + 8);
        cpa16(base + 3 * TILE_B + doff,      gBl);
        cpa16(base + 3 * TILE_B + doff + 16, gBl + 8);
        CP_COMMIT();
    }

    for (int it = 0; it < niter; it++) {
        if (it + 1 < niter) {
            int k0 = (it + 1) << 5;
            uint32_t base = sb + ((it + 1) & 1) * STAGE_B;
            cpa16(base + doff,                 gAh + k0);
            cpa16(base + doff + 16,            gAh + k0 + 8);
            cpa16(base + TILE_B + doff,        gAl + k0);
            cpa16(base + TILE_B + doff + 16,   gAl + k0 + 8);
            cpa16(base + 2 * TILE_B + doff,      gBh + k0);
            cpa16(base + 2 * TILE_B + doff + 16, gBh + k0 + 8);
            cpa16(base + 3 * TILE_B + doff,      gBl + k0);
            cpa16(base + 3 * TILE_B + doff + 16, gBl + k0 + 8);
            CP_COMMIT();
            CP_WAIT(1);
        } else {
            CP_WAIT(0);
        }
        __syncthreads();

        const char* st = smem + (it & 1) * STAGE_B;
        const char* sAh = st;
        const char* sAl = st + TILE_B;
        const char* sBh = st + 2 * TILE_B;
        const char* sBl = st + 3 * TILE_B;

#pragma unroll
        for (int kk = 0; kk < 32; kk += 16) {
            uint32_t ah[4][4], al[4][4], bh[4][2], bl[4][2];
#pragma unroll
            for (int mt = 0; mt < 4; mt++) {
                int r0 = wm * 64 + mt * 16 + gid;
                int ko = (kk + tig * 2) * 2;
                ah[mt][0] = *(const uint32_t*)(sAh + r0 * 80 + ko);
                ah[mt][1] = *(const uint32_t*)(sAh + (r0 + 8) * 80 + ko);
                ah[mt][2] = *(const uint32_t*)(sAh + r0 * 80 + ko + 16);
                ah[mt][3] = *(const uint32_t*)(sAh + (r0 + 8) * 80 + ko + 16);
                al[mt][0] = *(const uint32_t*)(sAl + r0 * 80 + ko);
                al[mt][1] = *(const uint32_t*)(sAl + (r0 + 8) * 80 + ko);
                al[mt][2] = *(const uint32_t*)(sAl + r0 * 80 + ko + 16);
                al[mt][3] = *(const uint32_t*)(sAl + (r0 + 8) * 80 + ko + 16);
            }
#pragma unroll
            for (int nt = 0; nt < 4; nt++) {
                int r0 = wn * 32 + nt * 8 + gid;
                int ko = (kk + tig * 2) * 2;
                bh[nt][0] = *(const uint32_t*)(sBh + r0 * 80 + ko);
                bh[nt][1] = *(const uint32_t*)(sBh + r0 * 80 + ko + 16);
                bl[nt][0] = *(const uint32_t*)(sBl + r0 * 80 + ko);
                bl[nt][1] = *(const uint32_t*)(sBl + r0 * 80 + ko + 16);
            }
#pragma unroll
            for (int mt = 0; mt < 4; mt++)
#pragma unroll
                for (int nt = 0; nt < 4; nt++) {
                    mma16816(acc[mt][nt], ah[mt], bh[nt]);
                    mma16816(acc[mt][nt], ah[mt], bl[nt]);
                    mma16816(acc[mt][nt], al[mt], bh[nt]);
                }
        }
        __syncthreads();
    }

    // epilogue
#pragma unroll
    for (int mt = 0; mt < 4; mt++) {
        int m = m0 + wm * 64 + mt * 16 + gid;
        float mk0 = rowmask ? rowmask[m] : 1.0f;
        float mk1 = rowmask ? rowmask[m + 8] : 1.0f;
#pragma unroll
        for (int nt = 0; nt < 4; nt++) {
            int n = n0 + wn * 32 + nt * 8 + tig * 2;
            float2 v0 = make_float2(acc[mt][nt][0] * mk0, acc[mt][nt][1] * mk0);
            float2 v1 = make_float2(acc[mt][nt][2] * mk1, acc[mt][nt][3] * mk1);
            *(float2*)&C[(size_t)m * ldc + n]       = v0;
            *(float2*)&C[(size_t)(m + 8) * ldc + n] = v1;
        }
    }
}

// ---------------- 7. cyclic RoPE + transpose to [B,H,L,DH] ------------------
__global__ void rope_k(const float* __restrict__ rope_freqs,
                       const int* __restrict__ residue_index,
                       const int* __restrict__ chain_index,
                       const float* __restrict__ cyclic_mask) {
    int row = blockIdx.x;          // b*L + l
    int b = row / LL, l = row % LL;
    int tid = threadIdx.x;

    __shared__ float cs[FF], sn[FF];
    if (tid < FF) {
        float t  = (float)residue_index[row];
        int   ci = chain_index[row];
        float cm = cyclic_mask[row];
        float a;
        if (cm > 0.0f) {
            float ring = g_counts[b * NC + ci] * cm;
            float rsafe = fmaxf(ring, 1.0f);
            float mk = fmaxf(floorf(rsafe * 0.5f), 1.0f);
            float kf = (float)(tid + 1);
            float keff = (mk == 1.0f) ? 1.0f : (1.0f + fmodf(kf - 1.0f, mk));
            float om = (TWO_PI_F * keff) / rsafe;
            a = om * t;
        } else {
            a = t * rope_freqs[tid] + (float)ci * rope_freqs[0];
        }
        sincosf(a, &sn[tid], &cs[tid]);
    }
    __syncthreads();

    const float2* q2 = (const float2*)(g_qkv + (size_t)row * 3072);
    const float2* k2 = q2 + 512;
    const float2* v2 = q2 + 1024;

#pragma unroll
    for (int i = 0; i < 4; i++) {
        int p = tid + i * 128;       // 0..511: pair index; h = p/32, f = p%32
        int h = p >> 5, f = p & 31;
        float c = cs[f], s = sn[f];
        float2 q = q2[p];
        float2 k = k2[p];
        float2 v = v2[p];
        size_t dst = ((size_t)(b * HH + h) * LL + l) * 32 + f;   // float2 idx
        ((float2*)g_q)[dst] = make_float2((q.x * c - q.y * s) * 0.125f,
                                          (q.y * c + q.x * s) * 0.125f);
        ((float2*)g_k)[dst] = make_float2(k.x * c - k.y * s,
                                          k.y * c + k.x * s);
        ((float2*)g_v)[dst] = v;
    }
}

// ---------------- 8. attention (flash-style, one query row per thread) ------
__global__ __launch_bounds__(64)
void attn_k(const float* __restrict__ seq_mask) {
    __shared__ float4 Ks[64 * 16];
    __shared__ float4 Vs[64 * 16];
    __shared__ float  km[64];

    int b = blockIdx.z, h = blockIdx.y, qt = blockIdx.x;
    int tid = threadIdx.x;
    size_t bh = (size_t)(b * HH + h);

    const float4* q4 = (const float4*)g_q + (bh * LL + qt * 64 + tid) * 16;
    float4 qf[16];
#pragma unroll
    for (int i = 0; i < 16; i++) qf[i] = q4[i];

    float4 of[16];
#pragma unroll
    for (int i = 0; i < 16; i++) of[i] = make_float4(0.f, 0.f, 0.f, 0.f);
    float m = -FLT_MAX, lsum = 0.0f;

    for (int kt = 0; kt < 16; kt++) {
        const float4* kk4 = (const float4*)g_k + (bh * LL + kt * 64) * 16;
        const float4* vv4 = (const float4*)g_v + (bh * LL + kt * 64) * 16;
#pragma unroll
        for (int i = 0; i < 16; i++) {
            Ks[tid + i * 64] = kk4[tid + i * 64];
            Vs[tid + i * 64] = vv4[tid + i * 64];
        }
        km[tid] = seq_mask[b * LL + kt * 64 + tid];
        __syncthreads();

        float sv[64];
        float tm = -FLT_MAX;
#pragma unroll
        for (int j = 0; j < 64; j++) {
            float s = 0.0f;
            const float4* kr = &Ks[j * 16];
#pragma unroll
            for (int d = 0; d < 16; d++) {
                float4 kv = kr[d];
                s += qf[d].x * kv.x + qf[d].y * kv.y +
                     qf[d].z * kv.z + qf[d].w * kv.w;
            }
            s = (km[j] > 0.0f) ? s : -FLT_MAX;
            sv[j] = s;
            tm = fmaxf(tm, s);
        }

        float mnew = fmaxf(m, tm);
        float corr = __expf(m - mnew);
        lsum *= corr;
#pragma unroll
        for (int d = 0; d < 16; d++) {
            of[d].x *= corr; of[d].y *= corr; of[d].z *= corr; of[d].w *= corr;
        }
#pragma unroll
        for (int j = 0; j < 64; j++) {
            float p = __expf(sv[j] - mnew);
            lsum += p;
            const float4* vr = &Vs[j * 16];
#pragma unroll
            for (int d = 0; d < 16; d++) {
                float4 vv = vr[d];
                of[d].x += p * vv.x; of[d].y += p * vv.y;
                of[d].z += p * vv.z; of[d].w += p * vv.w;
            }
        }
        m = mnew;
        __syncthreads();
    }

    float inv = 1.0f / lsum;
    // write split-bf16 ao at [b, l, h*64 .. h*64+63]
    size_t ebase = ((size_t)(b * LL + qt * 64 + tid)) * 1024 + h * 64;
    __nv_bfloat162* oh = (__nv_bfloat162*)(g_aoh + ebase);
    __nv_bfloat162* ol = (__nv_bfloat162*)(g_aol + ebase);
#pragma unroll
    for (int d = 0; d < 16; d++) {
        float4 v = of[d];
        v.x *= inv; v.y *= inv; v.z *= inv; v.w *= inv;
        __nv_bfloat16 hx = __float2bfloat16(v.x);
        __nv_bfloat16 hy = __float2bfloat16(v.y);
        __nv_bfloat16 hz = __float2bfloat16(v.z);
        __nv_bfloat16 hw = __float2bfloat16(v.w);
        __nv_bfloat162 h01, h23, l01, l23;
        h01.x = hx; h01.y = hy; h23.x = hz; h23.y = hw;
        l01.x = __float2bfloat16(v.x - __bfloat162float(hx));
        l01.y = __float2bfloat16(v.y - __bfloat162float(hy));
        l23.x = __float2bfloat16(v.z - __bfloat162float(hz));
        l23.y = __float2bfloat16(v.w - __bfloat162float(hw));
        oh[d * 2]     = h01;
        oh[d * 2 + 1] = h23;
        ol[d * 2]     = l01;
        ol[d * 2 + 1] = l23;
    }
}

// ---------------- launch ----------------------------------------------------
extern "C" void kernel_launch(void* const* d_in, const int* in_sizes, int n_in,
                              void* d_out, int out_size) {
    const float* x           = (const float*)d_in[0];
    const float* timep       = (const float*)d_in[1];
    const float* seq_mask    = (const float*)d_in[2];
    const float* cyclic_mask = (const float*)d_in[3];
    const float* gamma       = (const float*)d_in[4];
    const float* Wt          = (const float*)d_in[5];
    const float* bt          = (const float*)d_in[6];
    const float* Wq          = (const float*)d_in[7];
    const float* Wkv         = (const float*)d_in[8];
    const float* Wo          = (const float*)d_in[9];
    const float* rope_freqs  = (const float*)d_in[10];
    const int*   residue_idx = (const int*)d_in[11];
    const int*   chain_idx   = (const int*)d_in[12];
    float* out = (float*)d_out;

    cudaFuncSetAttribute(mma_gemm_k,
                         cudaFuncAttributeMaxDynamicSharedMemorySize, SM_TOT);

    __nv_bfloat16 *wh, *wl, *woh, *wol, *xh, *xl, *aoh, *aol;
    float *qkv;
    cudaGetSymbolAddress((void**)&wh,  g_wh);
    cudaGetSymbolAddress((void**)&wl,  g_wl);
    cudaGetSymbolAddress((void**)&woh, g_woh);
    cudaGetSymbolAddress((void**)&wol, g_wol);
    cudaGetSymbolAddress((void**)&xh,  g_xh);
    cudaGetSymbolAddress((void**)&xl,  g_xl);
    cudaGetSymbolAddress((void**)&aoh, g_aoh);
    cudaGetSymbolAddress((void**)&aol, g_aol);
    cudaGetSymbolAddress((void**)&qkv, g_qkv);

    silu_k<<<16, 256>>>(timep);
    zero_counts_k<<<1, 32>>>();
    count_k<<<16, 256>>>(chain_idx, cyclic_mask);
    ss_gemv_k<<<1024, 256>>>(Wt, bt);

    // weight splits: [Wq; Wkv] into g_wh/g_wl, Wo into g_woh/g_wol
    split_k<<<(1024 * 1024 / 4 + 255) / 256, 256>>>(Wq, wh, wl, 1024 * 1024 / 4);
    split_k<<<(2048 * 1024 / 4 + 255) / 256, 256>>>(Wkv, wh + 1024 * 1024,
                                                    wl + 1024 * 1024,
                                                    2048 * 1024 / 4);
    split_k<<<(1024 * 1024 / 4 + 255) / 256, 256>>>(Wo, woh, wol, 1024 * 1024 / 4);

    ln_mod_k<<<BB * LL, 256>>>(x, seq_mask, gamma);

    // fused qkv GEMM: [4096,1024] x [3072,1024]^T -> g_qkv [4096,3072]
    mma_gemm_k<<<dim3(24, 32), 256, SM_TOT>>>(xh, xl, wh, wl, qkv,
                                              1024, 3072, nullptr);

    rope_k<<<BB * LL, 128>>>(rope_freqs, residue_idx, chain_idx, cyclic_mask);

    attn_k<<<dim3(LL / 64, HH, BB), 64>>>(seq_mask);

    // out = ao @ Wo^T, masked: [4096,1024] x [1024,1024]^T
    mma_gemm_k<<<dim3(8, 32), 256, SM_TOT>>>(aoh, aol, woh, wol, out,
                                             1024, 1024, seq_mask);
}

// round 4
// speedup vs baseline: 3.6161x; 2.6285x over previous
#include <cuda_runtime.h>
#include <cuda_bf16.h>
#include <float.h>
#include <math.h>
#include <stdint.h>

// Problem constants (fixed shapes for this bench)
#define BB   4
#define LL   1024
#define DIMM 1024
#define HH   16
#define DHH  64
#define FF   32      // DH/2 rope frequencies
#define NC   2       // NUM_CHAINS
#define TWO_PI_F 6.2831853071795864769f

// ---------------- scratch (static device globals; no allocation) -----------
__device__ float g_st[BB * DIMM];                 // silu(time)
__device__ float g_ss[BB * 2 * DIMM];             // scale|shift per batch
__device__ float g_counts[BB * NC];               // cyclic counts per chain

// split-bf16 operands
__device__ __nv_bfloat16 g_xh[(size_t)BB * LL * DIMM];   // LN+mod output hi
__device__ __nv_bfloat16 g_xl[(size_t)BB * LL * DIMM];   // LN+mod output lo
__device__ __nv_bfloat16 g_wh[(size_t)3 * DIMM * DIMM];  // [Wq;Wkv] hi
__device__ __nv_bfloat16 g_wl[(size_t)3 * DIMM * DIMM];  // [Wq;Wkv] lo
__device__ __nv_bfloat16 g_woh[(size_t)DIMM * DIMM];     // Wo hi
__device__ __nv_bfloat16 g_wol[(size_t)DIMM * DIMM];     // Wo lo
__device__ __nv_bfloat16 g_aoh[(size_t)BB * LL * DIMM];  // attn out hi
__device__ __nv_bfloat16 g_aol[(size_t)BB * LL * DIMM];  // attn out lo

__device__ float g_qkv[(size_t)BB * LL * 3 * DIMM];      // fused q|k|v GEMM out

// rope'd split-bf16 q/k [B,H,L,DH] and transposed v [B,H,DH,L]
__device__ __nv_bfloat16 g_qh[(size_t)BB * HH * LL * DHH];
__device__ __nv_bfloat16 g_ql[(size_t)BB * HH * LL * DHH];
__device__ __nv_bfloat16 g_kh[(size_t)BB * HH * LL * DHH];
__device__ __nv_bfloat16 g_kl[(size_t)BB * HH * LL * DHH];
__device__ __nv_bfloat16 g_vth[(size_t)BB * HH * DHH * LL];
__device__ __nv_bfloat16 g_vtl[(size_t)BB * HH * DHH * LL];

// ============================================================================
// PTX helpers (base ISA only)
// ============================================================================
__device__ __forceinline__ uint32_t smem_u32(const void* p) {
    uint32_t a;
    asm("{ .reg .u64 t; cvta.to.shared.u64 t, %1; cvt.u32.u64 %0, t; }"
        : "=r"(a) : "l"(p));
    return a;
}
__device__ __forceinline__ void cpa16(uint32_t dst, const void* src) {
    asm volatile("cp.async.cg.shared.global [%0], [%1], 16;"
                 :: "r"(dst), "l"(src) : "memory");
}
#define CP_COMMIT() asm volatile("cp.async.commit_group;" ::: "memory")
#define CP_WAIT(N)  asm volatile("cp.async.wait_group %0;" :: "n"(N) : "memory")

__device__ __forceinline__ void mma16816(float* d, const uint32_t* a,
                                         const uint32_t* b) {
    asm volatile(
        "mma.sync.aligned.m16n8k16.row.col.f32.bf16.bf16.f32 "
        "{%0,%1,%2,%3}, {%4,%5,%6,%7}, {%8,%9}, {%0,%1,%2,%3};"
        : "+f"(d[0]), "+f"(d[1]), "+f"(d[2]), "+f"(d[3])
        : "r"(a[0]), "r"(a[1]), "r"(a[2]), "r"(a[3]), "r"(b[0]), "r"(b[1]));
}

__device__ __forceinline__ void split2(float x, float y,
                                       uint32_t& hi, uint32_t& lo) {
    __nv_bfloat16 hx = __float2bfloat16(x);
    __nv_bfloat16 hy = __float2bfloat16(y);
    __nv_bfloat162 h, l;
    h.x = hx; h.y = hy;
    l.x = __float2bfloat16(x - __bfloat162float(hx));
    l.y = __float2bfloat16(y - __bfloat162float(hy));
    hi = *(uint32_t*)&h;
    lo = *(uint32_t*)&l;
}

// ---------------- 1. silu(time) --------------------------------------------
__global__ void silu_k(const float* __restrict__ timep) {
    int i = blockIdx.x * 256 + threadIdx.x;
    if (i < BB * DIMM) {
        float t = timep[i];
        g_st[i] = t / (1.0f + expf(-t));
    }
}

// ---------------- 2. cyclic counts ------------------------------------------
__global__ void zero_counts_k() {
    if (threadIdx.x < BB * NC) g_counts[threadIdx.x] = 0.0f;
}
__global__ void count_k(const int* __restrict__ chain_index,
                        const float* __restrict__ cyclic_mask) {
    int i = blockIdx.x * 256 + threadIdx.x;
    if (i < BB * LL) {
        int b = i / LL;
        atomicAdd(&g_counts[b * NC + chain_index[i]], cyclic_mask[i]);
    }
}

// ---------------- 3. ss = silu(time) @ Wt^T + bt ----------------------------
__global__ void ss_gemv_k(const float* __restrict__ Wt,
                          const float* __restrict__ bt) {
    int warp = (blockIdx.x * blockDim.x + threadIdx.x) >> 5;
    int lane = threadIdx.x & 31;
    if (warp >= BB * 2 * DIMM) return;
    int b = warp / (2 * DIMM);
    int r = warp % (2 * DIMM);
    const float4* w4 = (const float4*)(Wt + (size_t)r * DIMM);
    const float4* s4 = (const float4*)(g_st + b * DIMM);
    float sum = 0.0f;
#pragma unroll
    for (int i = 0; i < 8; i++) {
        float4 w = w4[lane + i * 32];
        float4 s = s4[lane + i * 32];
        sum += w.x * s.x + w.y * s.y + w.z * s.z + w.w * s.w;
    }
#pragma unroll
    for (int o = 16; o; o >>= 1) sum += __shfl_down_sync(0xffffffffu, sum, o);
    if (lane == 0) g_ss[b * 2 * DIMM + r] = sum + bt[r];
}

// ---------------- 4. fp32 -> split bf16 conversion ---------------------------
__global__ void split_k(const float* __restrict__ src,
                        __nv_bfloat16* __restrict__ hi,
                        __nv_bfloat16* __restrict__ lo, int n4) {
    int i = blockIdx.x * 256 + threadIdx.x;
    if (i < n4) {
        float4 x = ((const float4*)src)[i];
        uint32_t h01, h23, l01, l23;
        split2(x.x, x.y, h01, l01);
        split2(x.z, x.w, h23, l23);
        ((uint32_t*)hi)[i * 2]     = h01;
        ((uint32_t*)hi)[i * 2 + 1] = h23;
        ((uint32_t*)lo)[i * 2]     = l01;
        ((uint32_t*)lo)[i * 2 + 1] = l23;
    }
}

// ---------------- 5. LayerNorm + modulation (writes split bf16) --------------
__global__ void ln_mod_k(const float* __restrict__ x,
                         const float* __restrict__ seq_mask,
                         const float* __restrict__ gamma) {
    int row = blockIdx.x;          // b*L + l
    int b   = row / LL;
    int tid = threadIdx.x;

    float mval = seq_mask[row];
    float4 xv = ((const float4*)x)[(size_t)row * 256 + tid];
    xv.x *= mval; xv.y *= mval; xv.z *= mval; xv.w *= mval;

    float s = xv.x + xv.y + xv.z + xv.w;
    float q = xv.x * xv.x + xv.y * xv.y + xv.z * xv.z + xv.w * xv.w;

    __shared__ float rs[256];
    __shared__ float rq[256];
    rs[tid] = s; rq[tid] = q;
    __syncthreads();
#pragma unroll
    for (int o = 128; o; o >>= 1) {
        if (tid < o) { rs[tid] += rs[tid + o]; rq[tid] += rq[tid + o]; }
        __syncthreads();
    }
    float mu   = rs[0] * (1.0f / DIMM);
    float var  = rq[0] * (1.0f / DIMM) - mu * mu;
    float rstd = rsqrtf(var + 1e-5f);

    float4 g  = ((const float4*)gamma)[tid];
    float4 sc = ((const float4*)g_ss)[b * 512 + tid];
    float4 sh = ((const float4*)g_ss)[b * 512 + 256 + tid];

    float4 o;
    o.x = (xv.x - mu) * rstd * g.x * (sc.x + 1.0f) + sh.x;
    o.y = (xv.y - mu) * rstd * g.y * (sc.y + 1.0f) + sh.y;
    o.z = (xv.z - mu) * rstd * g.z * (sc.z + 1.0f) + sh.z;
    o.w = (xv.w - mu) * rstd * g.w * (sc.w + 1.0f) + sh.w;

    uint32_t h01, h23, l01, l23;
    split2(o.x, o.y, h01, l01);
    split2(o.z, o.w, h23, l23);
    size_t p = (size_t)row * 512 + tid * 2;
    ((uint32_t*)g_xh)[p]     = h01;
    ((uint32_t*)g_xh)[p + 1] = h23;
    ((uint32_t*)g_xl)[p]     = l01;
    ((uint32_t*)g_xl)[p + 1] = l23;
}

// ---------------- 6. mma.sync split-bf16 GEMM: C = A @ B^T -------------------
#define TILE_B   10240                       // bytes per tile (128*40*2)
#define STAGE_B  (4 * TILE_B)                // Ah,Al,Bh,Bl
#define SM_TOT   (2 * STAGE_B)               // double buffered: 81920 B

__global__ __launch_bounds__(256)
void mma_gemm_k(const __nv_bfloat16* __restrict__ Ah,
                const __nv_bfloat16* __restrict__ Al,
                const __nv_bfloat16* __restrict__ Bh,
                const __nv_bfloat16* __restrict__ Bl,
                float* __restrict__ C, int K, int ldc,
                const float* __restrict__ rowmask) {
    extern __shared__ __align__(16) char smem[];
    const int tid  = threadIdx.x;
    const int wid  = tid >> 5;
    const int lane = tid & 31;
    const int gid  = lane >> 2;          // 0..7
    const int tig  = lane & 3;           // 0..3
    const int m0 = blockIdx.y * 128;
    const int n0 = blockIdx.x * 128;
    const int wm = wid & 1;              // 0..1  (m warp)
    const int wn = wid >> 1;             // 0..3  (n warp)

    uint32_t sb = smem_u32(smem);

    const int lrow = tid >> 1;
    const int lk   = (tid & 1) * 16;
    const __nv_bfloat16* gAh = Ah + (size_t)(m0 + lrow) * K + lk;
    const __nv_bfloat16* gAl = Al + (size_t)(m0 + lrow) * K + lk;
    const __nv_bfloat16* gBh = Bh + (size_t)(n0 + lrow) * K + lk;
    const __nv_bfloat16* gBl = Bl + (size_t)(n0 + lrow) * K + lk;
    const uint32_t doff = (uint32_t)lrow * 80 + (uint32_t)lk * 2;

    float acc[4][4][4];
#pragma unroll
    for (int a = 0; a < 4; a++)
#pragma unroll
        for (int b = 0; b < 4; b++)
#pragma unroll
            for (int c = 0; c < 4; c++) acc[a][b][c] = 0.0f;

    const int niter = K >> 5;

    {
        uint32_t base = sb;
        cpa16(base + doff,                 gAh);
        cpa16(base + doff + 16,            gAh + 8);
        cpa16(base + TILE_B + doff,        gAl);
        cpa16(base + TILE_B + doff + 16,   gAl + 8);
        cpa16(base + 2 * TILE_B + doff,      gBh);
        cpa16(base + 2 * TILE_B + doff + 16, gBh + 8);
        cpa16(base + 3 * TILE_B + doff,      gBl);
        cpa16(base + 3 * TILE_B + doff + 16, gBl + 8);
        CP_COMMIT();
    }

    for (int it = 0; it < niter; it++) {
        if (it + 1 < niter) {
            int k0 = (it + 1) << 5;
            uint32_t base = sb + ((it + 1) & 1) * STAGE_B;
            cpa16(base + doff,                 gAh + k0);
            cpa16(base + doff + 16,            gAh + k0 + 8);
            cpa16(base + TILE_B + doff,        gAl + k0);
            cpa16(base + TILE_B + doff + 16,   gAl + k0 + 8);
            cpa16(base + 2 * TILE_B + doff,      gBh + k0);
            cpa16(base + 2 * TILE_B + doff + 16, gBh + k0 + 8);
            cpa16(base + 3 * TILE_B + doff,      gBl + k0);
            cpa16(base + 3 * TILE_B + doff + 16, gBl + k0 + 8);
            CP_COMMIT();
            CP_WAIT(1);
        } else {
            CP_WAIT(0);
        }
        __syncthreads();

        const char* st = smem + (it & 1) * STAGE_B;
        const char* sAh = st;
        const char* sAl = st + TILE_B;
        const char* sBh = st + 2 * TILE_B;
        const char* sBl = st + 3 * TILE_B;

#pragma unroll
        for (int kk = 0; kk < 32; kk += 16) {
            uint32_t ah[4][4], al[4][4], bh[4][2], bl[4][2];
#pragma unroll
            for (int mt = 0; mt < 4; mt++) {
                int r0 = wm * 64 + mt * 16 + gid;
                int ko = (kk + tig * 2) * 2;
                ah[mt][0] = *(const uint32_t*)(sAh + r0 * 80 + ko);
                ah[mt][1] = *(const uint32_t*)(sAh + (r0 + 8) * 80 + ko);
                ah[mt][2] = *(const uint32_t*)(sAh + r0 * 80 + ko + 16);
                ah[mt][3] = *(const uint32_t*)(sAh + (r0 + 8) * 80 + ko + 16);
                al[mt][0] = *(const uint32_t*)(sAl + r0 * 80 + ko);
                al[mt][1] = *(const uint32_t*)(sAl + (r0 + 8) * 80 + ko);
                al[mt][2] = *(const uint32_t*)(sAl + r0 * 80 + ko + 16);
                al[mt][3] = *(const uint32_t*)(sAl + (r0 + 8) * 80 + ko + 16);
            }
#pragma unroll
            for (int nt = 0; nt < 4; nt++) {
                int r0 = wn * 32 + nt * 8 + gid;
                int ko = (kk + tig * 2) * 2;
                bh[nt][0] = *(const uint32_t*)(sBh + r0 * 80 + ko);
                bh[nt][1] = *(const uint32_t*)(sBh + r0 * 80 + ko + 16);
                bl[nt][0] = *(const uint32_t*)(sBl + r0 * 80 + ko);
                bl[nt][1] = *(const uint32_t*)(sBl + r0 * 80 + ko + 16);
            }
#pragma unroll
            for (int mt = 0; mt < 4; mt++)
#pragma unroll
                for (int nt = 0; nt < 4; nt++) {
                    mma16816(acc[mt][nt], ah[mt], bh[nt]);
                    mma16816(acc[mt][nt], ah[mt], bl[nt]);
                    mma16816(acc[mt][nt], al[mt], bh[nt]);
                }
        }
        __syncthreads();
    }

#pragma unroll
    for (int mt = 0; mt < 4; mt++) {
        int m = m0 + wm * 64 + mt * 16 + gid;
        float mk0 = rowmask ? rowmask[m] : 1.0f;
        float mk1 = rowmask ? rowmask[m + 8] : 1.0f;
#pragma unroll
        for (int nt = 0; nt < 4; nt++) {
            int n = n0 + wn * 32 + nt * 8 + tig * 2;
            float2 v0 = make_float2(acc[mt][nt][0] * mk0, acc[mt][nt][1] * mk0);
            float2 v1 = make_float2(acc[mt][nt][2] * mk1, acc[mt][nt][3] * mk1);
            *(float2*)&C[(size_t)m * ldc + n]       = v0;
            *(float2*)&C[(size_t)(m + 8) * ldc + n] = v1;
        }
    }
}

// ---------------- 7. cyclic RoPE -> split bf16 q/k [B,H,L,DH] ---------------
__global__ void rope_k(const float* __restrict__ rope_freqs,
                       const int* __restrict__ residue_index,
                       const int* __restrict__ chain_index,
                       const float* __restrict__ cyclic_mask) {
    int row = blockIdx.x;          // b*L + l
    int b = row / LL, l = row % LL;
    int tid = threadIdx.x;

    __shared__ float cs[FF], sn[FF];
    if (tid < FF) {
        float t  = (float)residue_index[row];
        int   ci = chain_index[row];
        float cm = cyclic_mask[row];
        float a;
        if (cm > 0.0f) {
            float ring = g_counts[b * NC + ci] * cm;
            float rsafe = fmaxf(ring, 1.0f);
            float mk = fmaxf(floorf(rsafe * 0.5f), 1.0f);
            float kf = (float)(tid + 1);
            float keff = (mk == 1.0f) ? 1.0f : (1.0f + fmodf(kf - 1.0f, mk));
            float om = (TWO_PI_F * keff) / rsafe;
            a = om * t;
        } else {
            a = t * rope_freqs[tid] + (float)ci * rope_freqs[0];
        }
        sincosf(a, &sn[tid], &cs[tid]);
    }
    __syncthreads();

    const float2* q2 = (const float2*)(g_qkv + (size_t)row * 3072);
    const float2* k2 = q2 + 512;

#pragma unroll
    for (int i = 0; i < 4; i++) {
        int p = tid + i * 128;       // pair index; h = p/32, f = p%32
        int h = p >> 5, f = p & 31;
        float c = cs[f], s = sn[f];
        float2 q = q2[p];
        float2 k = k2[p];
        float qx = (q.x * c - q.y * s) * 0.125f;
        float qy = (q.y * c + q.x * s) * 0.125f;
        float kx = k.x * c - k.y * s;
        float ky = k.y * c + k.x * s;
        size_t dst = ((size_t)(b * HH + h) * LL + l) * 32 + f;   // 4B units
        uint32_t hi, lo;
        split2(qx, qy, hi, lo);
        ((uint32_t*)g_qh)[dst] = hi;
        ((uint32_t*)g_ql)[dst] = lo;
        split2(kx, ky, hi, lo);
        ((uint32_t*)g_kh)[dst] = hi;
        ((uint32_t*)g_kl)[dst] = lo;
    }
}

// ---------------- 8. V transpose: qkv v-section -> split bf16 [B,H,DH,L] ----
__global__ void vtrans_k() {
    __shared__ float ts[64][65];
    int lt = blockIdx.x;           // l tile (64)
    int h  = blockIdx.y;
    int b  = blockIdx.z;
    int tid = threadIdx.x;

    int l  = tid >> 2;             // 0..63
    int d0 = (tid & 3) * 16;       // 0,16,32,48
    const float* src = g_qkv + ((size_t)(b * LL + lt * 64 + l)) * 3072 +
                       2048 + h * 64 + d0;
#pragma unroll
    for (int j = 0; j < 4; j++) {
        float4 v = *(const float4*)(src + j * 4);
        ts[d0 + j * 4 + 0][l] = v.x;
        ts[d0 + j * 4 + 1][l] = v.y;
        ts[d0 + j * 4 + 2][l] = v.z;
        ts[d0 + j * 4 + 3][l] = v.w;
    }
    __syncthreads();

    int d  = tid >> 2;
    int l0 = (tid & 3) * 16;
    uint32_t hbuf[8], lbuf[8];
#pragma unroll
    for (int j = 0; j < 8; j++) {
        float x = ts[d][l0 + j * 2];
        float y = ts[d][l0 + j * 2 + 1];
        split2(x, y, hbuf[j], lbuf[j]);
    }
    size_t dst = ((size_t)(b * HH + h) * DHH + d) * LL + lt * 64 + l0;
    *(uint4*)&g_vth[dst]     = *(uint4*)&hbuf[0];
    *(uint4*)&g_vth[dst + 8] = *(uint4*)&hbuf[4];
    *(uint4*)&g_vtl[dst]     = *(uint4*)&lbuf[0];
    *(uint4*)&g_vtl[dst + 8] = *(uint4*)&lbuf[4];
}

// ---------------- 9. flash attention with mma.sync (split-bf16) -------------
// CTA: 128 queries (8 warps x 16 rows), key tiles of 64, double-buffered smem.
#define AT_KSTR  144                       // bytes per row (64 bf16 + pad)
#define AT_TILE  (64 * AT_KSTR)            // 9216 B
#define AT_STAGE (4 * AT_TILE)             // Kh,Kl,Vh,Vl = 36864 B
#define AT_SMEM  (2 * AT_STAGE)            // 73728 B

__global__ __launch_bounds__(256)
void attn_mma_k(const float* __restrict__ seq_mask) {
    extern __shared__ __align__(16) char smem[];
    const int tid  = threadIdx.x;
    const int wid  = tid >> 5;
    const int lane = tid & 31;
    const int gid  = lane >> 2;
    const int tig  = lane & 3;
    const int b  = blockIdx.z;
    const int h  = blockIdx.y;
    const int qt = blockIdx.x;
    const size_t bh = (size_t)(b * HH + h);

    uint32_t sb = smem_u32(smem);

    // load Q fragments (16 rows per warp) from gmem split-bf16
    const int qr = qt * 128 + wid * 16;
    uint32_t qh[4][4], ql[4][4];
#pragma unroll
    for (int kc = 0; kc < 4; kc++) {
        size_t r0 = (bh * LL + qr + gid) * 64 + kc * 16 + tig * 2;
        size_t r1 = r0 + 8 * 64;
        qh[kc][0] = *(const uint32_t*)&g_qh[r0];
        qh[kc][1] = *(const uint32_t*)&g_qh[r1];
        qh[kc][2] = *(const uint32_t*)&g_qh[r0 + 8];
        qh[kc][3] = *(const uint32_t*)&g_qh[r1 + 8];
        ql[kc][0] = *(const uint32_t*)&g_ql[r0];
        ql[kc][1] = *(const uint32_t*)&g_ql[r1];
        ql[kc][2] = *(const uint32_t*)&g_ql[r0 + 8];
        ql[kc][3] = *(const uint32_t*)&g_ql[r1 + 8];
    }

    float O[8][4];
#pragma unroll
    for (int nt = 0; nt < 8; nt++)
#pragma unroll
        for (int c = 0; c < 4; c++) O[nt][c] = 0.0f;
    float m0 = -FLT_MAX, m1 = -FLT_MAX, l0s = 0.0f, l1s = 0.0f;

    // cp.async tile loader: 512 16B-chunks per tile, 2 per thread
    const int cr = tid >> 2;            // row 0..63 (cid = tid*2 -> row tid>>2)
    const int cc = (tid * 2) & 7;       // chunk 0..7 (pairs)
    const __nv_bfloat16* Kh_g = g_kh + (bh * LL) * 64;
    const __nv_bfloat16* Kl_g = g_kl + (bh * LL) * 64;
    const __nv_bfloat16* Vh_g = g_vth + (bh * DHH) * LL;
    const __nv_bfloat16* Vl_g = g_vtl + (bh * DHH) * LL;

#define AT_LOAD(stage, kt)                                                    \
    {                                                                         \
        uint32_t base = sb + (stage) * AT_STAGE;                              \
        uint32_t so = (uint32_t)cr * AT_KSTR + (uint32_t)cc * 16;             \
        const __nv_bfloat16* k_src = Kh_g + ((size_t)(kt) * 64 + cr) * 64 + cc * 8; \
        const __nv_bfloat16* kl_src = Kl_g + ((size_t)(kt) * 64 + cr) * 64 + cc * 8; \
        const __nv_bfloat16* v_src = Vh_g + (size_t)cr * LL + (kt) * 64 + cc * 8; \
        const __nv_bfloat16* vl_src = Vl_g + (size_t)cr * LL + (kt) * 64 + cc * 8; \
        cpa16(base + so, k_src);                                              \
        cpa16(base + so + 16, k_src + 8);                                     \
        cpa16(base + AT_TILE + so, kl_src);                                   \
        cpa16(base + AT_TILE + so + 16, kl_src + 8);                          \
        cpa16(base + 2 * AT_TILE + so, v_src);                                \
        cpa16(base + 2 * AT_TILE + so + 16, v_src + 8);                       \
        cpa16(base + 3 * AT_TILE + so, vl_src);                               \
        cpa16(base + 3 * AT_TILE + so + 16, vl_src + 8);                      \
        CP_COMMIT();                                                          \
    }

    AT_LOAD(0, 0);

    for (int kt = 0; kt < 16; kt++) {
        if (kt + 1 < 16) {
            AT_LOAD((kt + 1) & 1, kt + 1);
            CP_WAIT(1);
        } else {
            CP_WAIT(0);
        }
        __syncthreads();

        const char* st  = smem + (kt & 1) * AT_STAGE;
        const char* sKh = st;
        const char* sKl = st + AT_TILE;
        const char* sVh = st + 2 * AT_TILE;
        const char* sVl = st + 3 * AT_TILE;

        // ---- S = Q K^T (split-bf16, 3 products) ----
        float S[8][4];
#pragma unroll
        for (int nt = 0; nt < 8; nt++)
#pragma unroll
            for (int c = 0; c < 4; c++) S[nt][c] = 0.0f;

#pragma unroll
        for (int kc = 0; kc < 4; kc++) {
            int ko = (kc * 16 + tig * 2) * 2;
#pragma unroll
            for (int nt = 0; nt < 8; nt++) {
                int roff = (nt * 8 + gid) * AT_KSTR + ko;
                uint32_t bhv[2], blv[2];
                bhv[0] = *(const uint32_t*)(sKh + roff);
                bhv[1] = *(const uint32_t*)(sKh + roff + 16);
                blv[0] = *(const uint32_t*)(sKl + roff);
                blv[1] = *(const uint32_t*)(sKl + roff + 16);
                mma16816(S[nt], qh[kc], bhv);
                mma16816(S[nt], qh[kc], blv);
                mma16816(S[nt], ql[kc], bhv);
            }
        }

        // ---- mask ----
        const float* mrow = seq_mask + b * LL + kt * 64;
#pragma unroll
        for (int nt = 0; nt < 8; nt++) {
            float mk0 = __ldg(mrow + nt * 8 + tig * 2);
            float mk1 = __ldg(mrow + nt * 8 + tig * 2 + 1);
            if (mk0 <= 0.0f) { S[nt][0] = -1e30f; S[nt][2] = -1e30f; }
            if (mk1 <= 0.0f) { S[nt][1] = -1e30f; S[nt][3] = -1e30f; }
        }

        // ---- online softmax ----
        float t0 = -FLT_MAX, t1 = -FLT_MAX;
#pragma unroll
        for (int nt = 0; nt < 8; nt++) {
            t0 = fmaxf(t0, fmaxf(S[nt][0], S[nt][1]));
            t1 = fmaxf(t1, fmaxf(S[nt][2], S[nt][3]));
        }
        t0 = fmaxf(t0, __shfl_xor_sync(0xffffffffu, t0, 1));
        t0 = fmaxf(t0, __shfl_xor_sync(0xffffffffu, t0, 2));
        t1 = fmaxf(t1, __shfl_xor_sync(0xffffffffu, t1, 1));
        t1 = fmaxf(t1, __shfl_xor_sync(0xffffffffu, t1, 2));

        float mn0 = fmaxf(m0, t0);
        float mn1 = fmaxf(m1, t1);
        float cr0 = __expf(m0 - mn0);
        float cr1 = __expf(m1 - mn1);
        m0 = mn0; m1 = mn1;

        float ps0 = 0.0f, ps1 = 0.0f;
#pragma unroll
        for (int nt = 0; nt < 8; nt++) {
            S[nt][0] = __expf(S[nt][0] - mn0);
            S[nt][1] = __expf(S[nt][1] - mn0);
            S[nt][2] = __expf(S[nt][2] - mn1);
            S[nt][3] = __expf(S[nt][3] - mn1);
            ps0 += S[nt][0] + S[nt][1];
            ps1 += S[nt][2] + S[nt][3];
        }
        ps0 += __shfl_xor_sync(0xffffffffu, ps0, 1);
        ps0 += __shfl_xor_sync(0xffffffffu, ps0, 2);
        ps1 += __shfl_xor_sync(0xffffffffu, ps1, 1);
        ps1 += __shfl_xor_sync(0xffffffffu, ps1, 2);
        l0s = l0s * cr0 + ps0;
        l1s = l1s * cr1 + ps1;

#pragma unroll
        for (int nt = 0; nt < 8; nt++) {
            O[nt][0] *= cr0; O[nt][1] *= cr0;
            O[nt][2] *= cr1; O[nt][3] *= cr1;
        }

        // ---- O += P V (split-bf16, 3 products) ----
#pragma unroll
        for (int kc = 0; kc < 4; kc++) {
            uint32_t pa_h[4], pa_l[4];
            split2(S[2 * kc][0],     S[2 * kc][1],     pa_h[0], pa_l[0]);
            split2(S[2 * kc][2],     S[2 * kc][3],     pa_h[1], pa_l[1]);
            split2(S[2 * kc + 1][0], S[2 * kc + 1][1], pa_h[2], pa_l[2]);
            split2(S[2 * kc + 1][2], S[2 * kc + 1][3], pa_h[3], pa_l[3]);
            int ko = (kc * 16 + tig * 2) * 2;
#pragma unroll
            for (int nt = 0; nt < 8; nt++) {
                int roff = (nt * 8 + gid) * AT_KSTR + ko;
                uint32_t bhv[2], blv[2];
                bhv[0] = *(const uint32_t*)(sVh + roff);
                bhv[1] = *(const uint32_t*)(sVh + roff + 16);
                blv[0] = *(const uint32_t*)(sVl + roff);
                blv[1] = *(const uint32_t*)(sVl + roff + 16);
                mma16816(O[nt], pa_h, bhv);
                mma16816(O[nt], pa_h, blv);
                mma16816(O[nt], pa_l, bhv);
            }
        }
        __syncthreads();
    }

    // ---- epilogue: O/l -> split bf16 at [b, l, h*64+dh] ----
    float inv0 = 1.0f / l0s;
    float inv1 = 1.0f / l1s;
    size_t row0 = (size_t)(b * LL + qr + gid) * 1024 + h * 64;
    size_t row1 = row0 + 8 * 1024;
#pragma unroll
    for (int nt = 0; nt < 8; nt++) {
        uint32_t hi, lo;
        split2(O[nt][0] * inv0, O[nt][1] * inv0, hi, lo);
        *(uint32_t*)&g_aoh[row0 + nt * 8 + tig * 2] = hi;
        *(uint32_t*)&g_aol[row0 + nt * 8 + tig * 2] = lo;
        split2(O[nt][2] * inv1, O[nt][3] * inv1, hi, lo);
        *(uint32_t*)&g_aoh[row1 + nt * 8 + tig * 2] = hi;
        *(uint32_t*)&g_aol[row1 + nt * 8 + tig * 2] = lo;
    }
}

// ---------------- launch ----------------------------------------------------
extern "C" void kernel_launch(void* const* d_in, const int* in_sizes, int n_in,
                              void* d_out, int out_size) {
    const float* x           = (const float*)d_in[0];
    const float* timep       = (const float*)d_in[1];
    const float* seq_mask    = (const float*)d_in[2];
    const float* cyclic_mask = (const float*)d_in[3];
    const float* gamma       = (const float*)d_in[4];
    const float* Wt          = (const float*)d_in[5];
    const float* bt          = (const float*)d_in[6];
    const float* Wq          = (const float*)d_in[7];
    const float* Wkv         = (const float*)d_in[8];
    const float* Wo          = (const float*)d_in[9];
    const float* rope_freqs  = (const float*)d_in[10];
    const int*   residue_idx = (const int*)d_in[11];
    const int*   chain_idx   = (const int*)d_in[12];
    float* out = (float*)d_out;

    cudaFuncSetAttribute(mma_gemm_k,
                         cudaFuncAttributeMaxDynamicSharedMemorySize, SM_TOT);
    cudaFuncSetAttribute(attn_mma_k,
                         cudaFuncAttributeMaxDynamicSharedMemorySize, AT_SMEM);

    __nv_bfloat16 *wh, *wl, *woh, *wol, *xh, *xl, *aoh, *aol;
    float *qkv;
    cudaGetSymbolAddress((void**)&wh,  g_wh);
    cudaGetSymbolAddress((void**)&wl,  g_wl);
    cudaGetSymbolAddress((void**)&woh, g_woh);
    cudaGetSymbolAddress((void**)&wol, g_wol);
    cudaGetSymbolAddress((void**)&xh,  g_xh);
    cudaGetSymbolAddress((void**)&xl,  g_xl);
    cudaGetSymbolAddress((void**)&aoh, g_aoh);
    cudaGetSymbolAddress((void**)&aol, g_aol);
    cudaGetSymbolAddress((void**)&qkv, g_qkv);

    silu_k<<<16, 256>>>(timep);
    zero_counts_k<<<1, 32>>>();
    count_k<<<16, 256>>>(chain_idx, cyclic_mask);
    ss_gemv_k<<<1024, 256>>>(Wt, bt);

    split_k<<<(1024 * 1024 / 4 + 255) / 256, 256>>>(Wq, wh, wl, 1024 * 1024 / 4);
    split_k<<<(2048 * 1024 / 4 + 255) / 256, 256>>>(Wkv, wh + 1024 * 1024,
                                                    wl + 1024 * 1024,
                                                    2048 * 1024 / 4);
    split_k<<<(1024 * 1024 / 4 + 255) / 256, 256>>>(Wo, woh, wol, 1024 * 1024 / 4);

    ln_mod_k<<<BB * LL, 256>>>(x, seq_mask, gamma);

    // fused qkv GEMM: [4096,1024] x [3072,1024]^T -> g_qkv [4096,3072]
    mma_gemm_k<<<dim3(24, 32), 256, SM_TOT>>>(xh, xl, wh, wl, qkv,
                                              1024, 3072, nullptr);

    rope_k<<<BB * LL, 128>>>(rope_freqs, residue_idx, chain_idx, cyclic_mask);
    vtrans_k<<<dim3(LL / 64, HH, BB), 256>>>();

    attn_mma_k<<<dim3(LL / 128, HH, BB), 256, AT_SMEM>>>(seq_mask);

    // out = ao @ Wo^T, masked: [4096,1024] x [1024,1024]^T
    mma_gemm_k<<<dim3(8, 32), 256, SM_TOT>>>(aoh, aol, woh, wol, out,
                                             1024, 1024, seq_mask);
}

// round 5
// speedup vs baseline: 4.6237x; 1.2786x over previous
#include <cuda_runtime.h>
#include <cuda_fp16.h>
#include <float.h>
#include <math.h>
#include <stdint.h>

// Problem constants (fixed shapes for this bench)
#define BB   4
#define LL   1024
#define DIMM 1024
#define HH   16
#define DHH  64
#define FF   32      // DH/2 rope frequencies
#define NC   2       // NUM_CHAINS
#define TWO_PI_F 6.2831853071795864769f

// ---------------- scratch (static device globals; no allocation) -----------
__device__ float g_st[BB * DIMM];                 // silu(time)
__device__ float g_ss[BB * 2 * DIMM];             // scale|shift per batch
__device__ float g_counts[BB * NC];               // cyclic counts per chain

// split-fp16 operands (A-side keeps hi+lo; B-side hi only)
__device__ __half g_xh[(size_t)BB * LL * DIMM];   // LN+mod output hi
__device__ __half g_xl[(size_t)BB * LL * DIMM];   // LN+mod output lo
__device__ __half g_wh[(size_t)3 * DIMM * DIMM];  // [Wq;Wkv] hi
__device__ __half g_woh[(size_t)DIMM * DIMM];     // Wo hi
__device__ __half g_aoh[(size_t)BB * LL * DIMM];  // attn out hi
__device__ __half g_aol[(size_t)BB * LL * DIMM];  // attn out lo

__device__ float g_qkv[(size_t)BB * LL * 3 * DIMM];      // fused q|k|v GEMM out

// rope'd q (hi+lo) / k (hi) [B,H,L,DH], transposed v hi [B,H,DH,L]
__device__ __half g_qh[(size_t)BB * HH * LL * DHH];
__device__ __half g_ql[(size_t)BB * HH * LL * DHH];
__device__ __half g_kh[(size_t)BB * HH * LL * DHH];
__device__ __half g_vth[(size_t)BB * HH * DHH * LL];

// ============================================================================
// PTX helpers (base ISA only)
// ============================================================================
__device__ __forceinline__ uint32_t smem_u32(const void* p) {
    uint32_t a;
    asm("{ .reg .u64 t; cvta.to.shared.u64 t, %1; cvt.u32.u64 %0, t; }"
        : "=r"(a) : "l"(p));
    return a;
}
__device__ __forceinline__ void cpa16(uint32_t dst, const void* src) {
    asm volatile("cp.async.cg.shared.global [%0], [%1], 16;"
                 :: "r"(dst), "l"(src) : "memory");
}
#define CP_COMMIT() asm volatile("cp.async.commit_group;" ::: "memory")
#define CP_WAIT(N)  asm volatile("cp.async.wait_group %0;" :: "n"(N) : "memory")

__device__ __forceinline__ void mma16816(float* d, const uint32_t* a,
                                         const uint32_t* b) {
    asm volatile(
        "mma.sync.aligned.m16n8k16.row.col.f32.f16.f16.f32 "
        "{%0,%1,%2,%3}, {%4,%5,%6,%7}, {%8,%9}, {%0,%1,%2,%3};"
        : "+f"(d[0]), "+f"(d[1]), "+f"(d[2]), "+f"(d[3])
        : "r"(a[0]), "r"(a[1]), "r"(a[2]), "r"(a[3]), "r"(b[0]), "r"(b[1]));
}

__device__ __forceinline__ void split2(float x, float y,
                                       uint32_t& hi, uint32_t& lo) {
    __half hx = __float2half_rn(x);
    __half hy = __float2half_rn(y);
    __half2 h, l;
    h.x = hx; h.y = hy;
    l.x = __float2half_rn(x - __half2float(hx));
    l.y = __float2half_rn(y - __half2float(hy));
    hi = *(uint32_t*)&h;
    lo = *(uint32_t*)&l;
}
__device__ __forceinline__ uint32_t pack2h(float x, float y) {
    __half2 h;
    h.x = __float2half_rn(x);
    h.y = __float2half_rn(y);
    return *(uint32_t*)&h;
}

// ---------------- 1. silu(time) --------------------------------------------
__global__ void silu_k(const float* __restrict__ timep) {
    int i = blockIdx.x * 256 + threadIdx.x;
    if (i < BB * DIMM) {
        float t = timep[i];
        g_st[i] = t / (1.0f + expf(-t));
    }
}

// ---------------- 2. cyclic counts ------------------------------------------
__global__ void zero_counts_k() {
    if (threadIdx.x < BB * NC) g_counts[threadIdx.x] = 0.0f;
}
__global__ void count_k(const int* __restrict__ chain_index,
                        const float* __restrict__ cyclic_mask) {
    int i = blockIdx.x * 256 + threadIdx.x;
    if (i < BB * LL) {
        int b = i / LL;
        atomicAdd(&g_counts[b * NC + chain_index[i]], cyclic_mask[i]);
    }
}

// ---------------- 3. ss = silu(time) @ Wt^T + bt ----------------------------
__global__ void ss_gemv_k(const float* __restrict__ Wt,
                          const float* __restrict__ bt) {
    int warp = (blockIdx.x * blockDim.x + threadIdx.x) >> 5;
    int lane = threadIdx.x & 31;
    if (warp >= BB * 2 * DIMM) return;
    int b = warp / (2 * DIMM);
    int r = warp % (2 * DIMM);
    const float4* w4 = (const float4*)(Wt + (size_t)r * DIMM);
    const float4* s4 = (const float4*)(g_st + b * DIMM);
    float sum = 0.0f;
#pragma unroll
    for (int i = 0; i < 8; i++) {
        float4 w = w4[lane + i * 32];
        float4 s = s4[lane + i * 32];
        sum += w.x * s.x + w.y * s.y + w.z * s.z + w.w * s.w;
    }
#pragma unroll
    for (int o = 16; o; o >>= 1) sum += __shfl_down_sync(0xffffffffu, sum, o);
    if (lane == 0) g_ss[b * 2 * DIMM + r] = sum + bt[r];
}

// ---------------- 4. fp32 -> fp16 (hi only, for weights) --------------------
__global__ void tohalf_k(const float* __restrict__ src,
                         __half* __restrict__ dst, int n4) {
    int i = blockIdx.x * 256 + threadIdx.x;
    if (i < n4) {
        float4 x = ((const float4*)src)[i];
        ((uint32_t*)dst)[i * 2]     = pack2h(x.x, x.y);
        ((uint32_t*)dst)[i * 2 + 1] = pack2h(x.z, x.w);
    }
}

// ---------------- 5. LayerNorm + modulation (writes split fp16) -------------
__global__ void ln_mod_k(const float* __restrict__ x,
                         const float* __restrict__ seq_mask,
                         const float* __restrict__ gamma) {
    int row = blockIdx.x;          // b*L + l
    int b   = row / LL;
    int tid = threadIdx.x;

    float mval = seq_mask[row];
    float4 xv = ((const float4*)x)[(size_t)row * 256 + tid];
    xv.x *= mval; xv.y *= mval; xv.z *= mval; xv.w *= mval;

    float s = xv.x + xv.y + xv.z + xv.w;
    float q = xv.x * xv.x + xv.y * xv.y + xv.z * xv.z + xv.w * xv.w;

    __shared__ float rs[256];
    __shared__ float rq[256];
    rs[tid] = s; rq[tid] = q;
    __syncthreads();
#pragma unroll
    for (int o = 128; o; o >>= 1) {
        if (tid < o) { rs[tid] += rs[tid + o]; rq[tid] += rq[tid + o]; }
        __syncthreads();
    }
    float mu   = rs[0] * (1.0f / DIMM);
    float var  = rq[0] * (1.0f / DIMM) - mu * mu;
    float rstd = rsqrtf(var + 1e-5f);

    float4 g  = ((const float4*)gamma)[tid];
    float4 sc = ((const float4*)g_ss)[b * 512 + tid];
    float4 sh = ((const float4*)g_ss)[b * 512 + 256 + tid];

    float4 o;
    o.x = (xv.x - mu) * rstd * g.x * (sc.x + 1.0f) + sh.x;
    o.y = (xv.y - mu) * rstd * g.y * (sc.y + 1.0f) + sh.y;
    o.z = (xv.z - mu) * rstd * g.z * (sc.z + 1.0f) + sh.z;
    o.w = (xv.w - mu) * rstd * g.w * (sc.w + 1.0f) + sh.w;

    uint32_t h01, h23, l01, l23;
    split2(o.x, o.y, h01, l01);
    split2(o.z, o.w, h23, l23);
    size_t p = (size_t)row * 512 + tid * 2;
    ((uint32_t*)g_xh)[p]     = h01;
    ((uint32_t*)g_xh)[p + 1] = h23;
    ((uint32_t*)g_xl)[p]     = l01;
    ((uint32_t*)g_xl)[p + 1] = l23;
}

// ---------------- 6. mma.sync split-fp16 GEMM: C = A @ B^T ------------------
// A hi+lo, B hi only. 2 products: Ah*Bh + Al*Bh. Tile 128x128, BK=32, 8 warps.
#define TILE_B   10240                       // bytes per tile (128*40*2)
#define STAGE_B  (3 * TILE_B)                // Ah,Al,Bh = 30720 B
#define SM_TOT   (2 * STAGE_B)               // double buffered: 61440 B

__global__ __launch_bounds__(256)
void mma_gemm_k(const __half* __restrict__ Ah,
                const __half* __restrict__ Al,
                const __half* __restrict__ Bh,
                float* __restrict__ C, int K, int ldc,
                const float* __restrict__ rowmask) {
    extern __shared__ __align__(16) char smem[];
    const int tid  = threadIdx.x;
    const int wid  = tid >> 5;
    const int lane = tid & 31;
    const int gid  = lane >> 2;          // 0..7
    const int tig  = lane & 3;           // 0..3
    const int m0 = blockIdx.y * 128;
    const int n0 = blockIdx.x * 128;
    const int wm = wid & 1;              // 0..1  (m warp)
    const int wn = wid >> 1;             // 0..3  (n warp)

    uint32_t sb = smem_u32(smem);

    const int lrow = tid >> 1;
    const int lk   = (tid & 1) * 16;
    const __half* gAh = Ah + (size_t)(m0 + lrow) * K + lk;
    const __half* gAl = Al + (size_t)(m0 + lrow) * K + lk;
    const __half* gBh = Bh + (size_t)(n0 + lrow) * K + lk;
    const uint32_t doff = (uint32_t)lrow * 80 + (uint32_t)lk * 2;

    float acc[4][4][4];
#pragma unroll
    for (int a = 0; a < 4; a++)
#pragma unroll
        for (int b = 0; b < 4; b++)
#pragma unroll
            for (int c = 0; c < 4; c++) acc[a][b][c] = 0.0f;

    const int niter = K >> 5;

    {
        uint32_t base = sb;
        cpa16(base + doff,                 gAh);
        cpa16(base + doff + 16,            gAh + 8);
        cpa16(base + TILE_B + doff,        gAl);
        cpa16(base + TILE_B + doff + 16,   gAl + 8);
        cpa16(base + 2 * TILE_B + doff,      gBh);
        cpa16(base + 2 * TILE_B + doff + 16, gBh + 8);
        CP_COMMIT();
    }

    for (int it = 0; it < niter; it++) {
        if (it + 1 < niter) {
            int k0 = (it + 1) << 5;
            uint32_t base = sb + ((it + 1) & 1) * STAGE_B;
            cpa16(base + doff,                 gAh + k0);
            cpa16(base + doff + 16,            gAh + k0 + 8);
            cpa16(base + TILE_B + doff,        gAl + k0);
            cpa16(base + TILE_B + doff + 16,   gAl + k0 + 8);
            cpa16(base + 2 * TILE_B + doff,      gBh + k0);
            cpa16(base + 2 * TILE_B + doff + 16, gBh + k0 + 8);
            CP_COMMIT();
            CP_WAIT(1);
        } else {
            CP_WAIT(0);
        }
        __syncthreads();

        const char* st = smem + (it & 1) * STAGE_B;
        const char* sAh = st;
        const char* sAl = st + TILE_B;
        const char* sBh = st + 2 * TILE_B;

#pragma unroll
        for (int kk = 0; kk < 32; kk += 16) {
            uint32_t ah[4][4], al[4][4], bh[4][2];
#pragma unroll
            for (int mt = 0; mt < 4; mt++) {
                int r0 = wm * 64 + mt * 16 + gid;
                int ko = (kk + tig * 2) * 2;
                ah[mt][0] = *(const uint32_t*)(sAh + r0 * 80 + ko);
                ah[mt][1] = *(const uint32_t*)(sAh + (r0 + 8) * 80 + ko);
                ah[mt][2] = *(const uint32_t*)(sAh + r0 * 80 + ko + 16);
                ah[mt][3] = *(const uint32_t*)(sAh + (r0 + 8) * 80 + ko + 16);
                al[mt][0] = *(const uint32_t*)(sAl + r0 * 80 + ko);
                al[mt][1] = *(const uint32_t*)(sAl + (r0 + 8) * 80 + ko);
                al[mt][2] = *(const uint32_t*)(sAl + r0 * 80 + ko + 16);
                al[mt][3] = *(const uint32_t*)(sAl + (r0 + 8) * 80 + ko + 16);
            }
#pragma unroll
            for (int nt = 0; nt < 4; nt++) {
                int r0 = wn * 32 + nt * 8 + gid;
                int ko = (kk + tig * 2) * 2;
                bh[nt][0] = *(const uint32_t*)(sBh + r0 * 80 + ko);
                bh[nt][1] = *(const uint32_t*)(sBh + r0 * 80 + ko + 16);
            }
#pragma unroll
            for (int mt = 0; mt < 4; mt++)
#pragma unroll
                for (int nt = 0; nt < 4; nt++) {
                    mma16816(acc[mt][nt], ah[mt], bh[nt]);
                    mma16816(acc[mt][nt], al[mt], bh[nt]);
                }
        }
        __syncthreads();
    }

#pragma unroll
    for (int mt = 0; mt < 4; mt++) {
        int m = m0 + wm * 64 + mt * 16 + gid;
        float mk0 = rowmask ? rowmask[m] : 1.0f;
        float mk1 = rowmask ? rowmask[m + 8] : 1.0f;
#pragma unroll
        for (int nt = 0; nt < 4; nt++) {
            int n = n0 + wn * 32 + nt * 8 + tig * 2;
            float2 v0 = make_float2(acc[mt][nt][0] * mk0, acc[mt][nt][1] * mk0);
            float2 v1 = make_float2(acc[mt][nt][2] * mk1, acc[mt][nt][3] * mk1);
            *(float2*)&C[(size_t)m * ldc + n]       = v0;
            *(float2*)&C[(size_t)(m + 8) * ldc + n] = v1;
        }
    }
}

// ---------------- 7. cyclic RoPE -> split fp16 q (hi+lo), k (hi) ------------
__global__ void rope_k(const float* __restrict__ rope_freqs,
                       const int* __restrict__ residue_index,
                       const int* __restrict__ chain_index,
                       const float* __restrict__ cyclic_mask) {
    int row = blockIdx.x;          // b*L + l
    int b = row / LL, l = row % LL;
    int tid = threadIdx.x;

    __shared__ float cs[FF], sn[FF];
    if (tid < FF) {
        float t  = (float)residue_index[row];
        int   ci = chain_index[row];
        float cm = cyclic_mask[row];
        float a;
        if (cm > 0.0f) {
            float ring = g_counts[b * NC + ci] * cm;
            float rsafe = fmaxf(ring, 1.0f);
            float mk = fmaxf(floorf(rsafe * 0.5f), 1.0f);
            float kf = (float)(tid + 1);
            float keff = (mk == 1.0f) ? 1.0f : (1.0f + fmodf(kf - 1.0f, mk));
            float om = (TWO_PI_F * keff) / rsafe;
            a = om * t;
        } else {
            a = t * rope_freqs[tid] + (float)ci * rope_freqs[0];
        }
        sincosf(a, &sn[tid], &cs[tid]);
    }
    __syncthreads();

    const float2* q2 = (const float2*)(g_qkv + (size_t)row * 3072);
    const float2* k2 = q2 + 512;

#pragma unroll
    for (int i = 0; i < 4; i++) {
        int p = tid + i * 128;       // pair index; h = p/32, f = p%32
        int h = p >> 5, f = p & 31;
        float c = cs[f], s = sn[f];
        float2 q = q2[p];
        float2 k = k2[p];
        float qx = (q.x * c - q.y * s) * 0.125f;
        float qy = (q.y * c + q.x * s) * 0.125f;
        float kx = k.x * c - k.y * s;
        float ky = k.y * c + k.x * s;
        size_t dst = ((size_t)(b * HH + h) * LL + l) * 32 + f;   // 4B units
        uint32_t hi, lo;
        split2(qx, qy, hi, lo);
        ((uint32_t*)g_qh)[dst] = hi;
        ((uint32_t*)g_ql)[dst] = lo;
        ((uint32_t*)g_kh)[dst] = pack2h(kx, ky);
    }
}

// ---------------- 8. V transpose: qkv v-section -> fp16 hi [B,H,DH,L] -------
__global__ void vtrans_k() {
    __shared__ float ts[64][65];
    int lt = blockIdx.x;           // l tile (64)
    int h  = blockIdx.y;
    int b  = blockIdx.z;
    int tid = threadIdx.x;

    int l  = tid >> 2;             // 0..63
    int d0 = (tid & 3) * 16;       // 0,16,32,48
    const float* src = g_qkv + ((size_t)(b * LL + lt * 64 + l)) * 3072 +
                       2048 + h * 64 + d0;
#pragma unroll
    for (int j = 0; j < 4; j++) {
        float4 v = *(const float4*)(src + j * 4);
        ts[d0 + j * 4 + 0][l] = v.x;
        ts[d0 + j * 4 + 1][l] = v.y;
        ts[d0 + j * 4 + 2][l] = v.z;
        ts[d0 + j * 4 + 3][l] = v.w;
    }
    __syncthreads();

    int d  = tid >> 2;
    int l0 = (tid & 3) * 16;
    uint32_t hbuf[8];
#pragma unroll
    for (int j = 0; j < 8; j++)
        hbuf[j] = pack2h(ts[d][l0 + j * 2], ts[d][l0 + j * 2 + 1]);
    size_t dst = ((size_t)(b * HH + h) * DHH + d) * LL + lt * 64 + l0;
    *(uint4*)&g_vth[dst]     = *(uint4*)&hbuf[0];
    *(uint4*)&g_vth[dst + 8] = *(uint4*)&hbuf[4];
}

// ---------------- 9. flash attention, mma.sync split-fp16 (2 products) ------
// CTA: 128 queries (8 warps x 16 rows), key tiles of 64, double-buffered smem.
#define AT_KSTR  144                       // bytes per row (64 fp16 + pad)
#define AT_TILE  (64 * AT_KSTR)            // 9216 B
#define AT_STAGE (2 * AT_TILE)             // Kh,Vh = 18432 B
#define AT_SMEM  (2 * AT_STAGE)            // 36864 B

__global__ __launch_bounds__(256)
void attn_mma_k(const float* __restrict__ seq_mask) {
    extern __shared__ __align__(16) char smem[];
    const int tid  = threadIdx.x;
    const int wid  = tid >> 5;
    const int lane = tid & 31;
    const int gid  = lane >> 2;
    const int tig  = lane & 3;
    const int b  = blockIdx.z;
    const int h  = blockIdx.y;
    const int qt = blockIdx.x;
    const size_t bh = (size_t)(b * HH + h);

    uint32_t sb = smem_u32(smem);

    // load Q fragments (16 rows per warp) from gmem split-fp16
    const int qr = qt * 128 + wid * 16;
    uint32_t qh[4][4], ql[4][4];
#pragma unroll
    for (int kc = 0; kc < 4; kc++) {
        size_t r0 = (bh * LL + qr + gid) * 64 + kc * 16 + tig * 2;
        size_t r1 = r0 + 8 * 64;
        qh[kc][0] = *(const uint32_t*)&g_qh[r0];
        qh[kc][1] = *(const uint32_t*)&g_qh[r1];
        qh[kc][2] = *(const uint32_t*)&g_qh[r0 + 8];
        qh[kc][3] = *(const uint32_t*)&g_qh[r1 + 8];
        ql[kc][0] = *(const uint32_t*)&g_ql[r0];
        ql[kc][1] = *(const uint32_t*)&g_ql[r1];
        ql[kc][2] = *(const uint32_t*)&g_ql[r0 + 8];
        ql[kc][3] = *(const uint32_t*)&g_ql[r1 + 8];
    }

    float O[8][4];
#pragma unroll
    for (int nt = 0; nt < 8; nt++)
#pragma unroll
        for (int c = 0; c < 4; c++) O[nt][c] = 0.0f;
    float m0 = -FLT_MAX, m1 = -FLT_MAX, l0s = 0.0f, l1s = 0.0f;

    const int cr = tid >> 2;            // row 0..63
    const int cc = (tid * 2) & 7;       // chunk pair
    const __half* Kh_g = g_kh + (bh * LL) * 64;
    const __half* Vh_g = g_vth + (bh * DHH) * LL;

#define AT_LOAD(stage, kt)                                                    \
    {                                                                         \
        uint32_t base = sb + (stage) * AT_STAGE;                              \
        uint32_t so = (uint32_t)cr * AT_KSTR + (uint32_t)cc * 16;             \
        const __half* k_src = Kh_g + ((size_t)(kt) * 64 + cr) * 64 + cc * 8;  \
        const __half* v_src = Vh_g + (size_t)cr * LL + (kt) * 64 + cc * 8;    \
        cpa16(base + so, k_src);                                              \
        cpa16(base + so + 16, k_src + 8);                                     \
        cpa16(base + AT_TILE + so, v_src);                                    \
        cpa16(base + AT_TILE + so + 16, v_src + 8);                           \
        CP_COMMIT();                                                          \
    }

    AT_LOAD(0, 0);

    for (int kt = 0; kt < 16; kt++) {
        if (kt + 1 < 16) {
            AT_LOAD((kt + 1) & 1, kt + 1);
            CP_WAIT(1);
        } else {
            CP_WAIT(0);
        }
        __syncthreads();

        const char* st  = smem + (kt & 1) * AT_STAGE;
        const char* sKh = st;
        const char* sVh = st + AT_TILE;

        // ---- S = Q K^T (2 products) ----
        float S[8][4];
#pragma unroll
        for (int nt = 0; nt < 8; nt++)
#pragma unroll
            for (int c = 0; c < 4; c++) S[nt][c] = 0.0f;

#pragma unroll
        for (int kc = 0; kc < 4; kc++) {
            int ko = (kc * 16 + tig * 2) * 2;
#pragma unroll
            for (int nt = 0; nt < 8; nt++) {
                int roff = (nt * 8 + gid) * AT_KSTR + ko;
                uint32_t bhv[2];
                bhv[0] = *(const uint32_t*)(sKh + roff);
                bhv[1] = *(const uint32_t*)(sKh + roff + 16);
                mma16816(S[nt], qh[kc], bhv);
                mma16816(S[nt], ql[kc], bhv);
            }
        }

        // ---- mask ----
        const float* mrow = seq_mask + b * LL + kt * 64;
#pragma unroll
        for (int nt = 0; nt < 8; nt++) {
            float mk0 = __ldg(mrow + nt * 8 + tig * 2);
            float mk1 = __ldg(mrow + nt * 8 + tig * 2 + 1);
            if (mk0 <= 0.0f) { S[nt][0] = -1e30f; S[nt][2] = -1e30f; }
            if (mk1 <= 0.0f) { S[nt][1] = -1e30f; S[nt][3] = -1e30f; }
        }

        // ---- online softmax ----
        float t0 = -FLT_MAX, t1 = -FLT_MAX;
#pragma unroll
        for (int nt = 0; nt < 8; nt++) {
            t0 = fmaxf(t0, fmaxf(S[nt][0], S[nt][1]));
            t1 = fmaxf(t1, fmaxf(S[nt][2], S[nt][3]));
        }
        t0 = fmaxf(t0, __shfl_xor_sync(0xffffffffu, t0, 1));
        t0 = fmaxf(t0, __shfl_xor_sync(0xffffffffu, t0, 2));
        t1 = fmaxf(t1, __shfl_xor_sync(0xffffffffu, t1, 1));
        t1 = fmaxf(t1, __shfl_xor_sync(0xffffffffu, t1, 2));

        float mn0 = fmaxf(m0, t0);
        float mn1 = fmaxf(m1, t1);
        float cr0 = __expf(m0 - mn0);
        float cr1 = __expf(m1 - mn1);
        m0 = mn0; m1 = mn1;

        float ps0 = 0.0f, ps1 = 0.0f;
#pragma unroll
        for (int nt = 0; nt < 8; nt++) {
            S[nt][0] = __expf(S[nt][0] - mn0);
            S[nt][1] = __expf(S[nt][1] - mn0);
            S[nt][2] = __expf(S[nt][2] - mn1);
            S[nt][3] = __expf(S[nt][3] - mn1);
            ps0 += S[nt][0] + S[nt][1];
            ps1 += S[nt][2] + S[nt][3];
        }
        ps0 += __shfl_xor_sync(0xffffffffu, ps0, 1);
        ps0 += __shfl_xor_sync(0xffffffffu, ps0, 2);
        ps1 += __shfl_xor_sync(0xffffffffu, ps1, 1);
        ps1 += __shfl_xor_sync(0xffffffffu, ps1, 2);
        l0s = l0s * cr0 + ps0;
        l1s = l1s * cr1 + ps1;

#pragma unroll
        for (int nt = 0; nt < 8; nt++) {
            O[nt][0] *= cr0; O[nt][1] *= cr0;
            O[nt][2] *= cr1; O[nt][3] *= cr1;
        }

        // ---- O += P V (2 products) ----
#pragma unroll
        for (int kc = 0; kc < 4; kc++) {
            uint32_t pa_h[4], pa_l[4];
            split2(S[2 * kc][0],     S[2 * kc][1],     pa_h[0], pa_l[0]);
            split2(S[2 * kc][2],     S[2 * kc][3],     pa_h[1], pa_l[1]);
            split2(S[2 * kc + 1][0], S[2 * kc + 1][1], pa_h[2], pa_l[2]);
            split2(S[2 * kc + 1][2], S[2 * kc + 1][3], pa_h[3], pa_l[3]);
            int ko = (kc * 16 + tig * 2) * 2;
#pragma unroll
            for (int nt = 0; nt < 8; nt++) {
                int roff = (nt * 8 + gid) * AT_KSTR + ko;
                uint32_t bhv[2];
                bhv[0] = *(const uint32_t*)(sVh + roff);
                bhv[1] = *(const uint32_t*)(sVh + roff + 16);
                mma16816(O[nt], pa_h, bhv);
                mma16816(O[nt], pa_l, bhv);
            }
        }
        __syncthreads();
    }

    // ---- epilogue: O/l -> split fp16 at [b, l, h*64+dh] ----
    float inv0 = 1.0f / l0s;
    float inv1 = 1.0f / l1s;
    size_t row0 = (size_t)(b * LL + qr + gid) * 1024 + h * 64;
    size_t row1 = row0 + 8 * 1024;
#pragma unroll
    for (int nt = 0; nt < 8; nt++) {
        uint32_t hi, lo;
        split2(O[nt][0] * inv0, O[nt][1] * inv0, hi, lo);
        *(uint32_t*)&g_aoh[row0 + nt * 8 + tig * 2] = hi;
        *(uint32_t*)&g_aol[row0 + nt * 8 + tig * 2] = lo;
        split2(O[nt][2] * inv1, O[nt][3] * inv1, hi, lo);
        *(uint32_t*)&g_aoh[row1 + nt * 8 + tig * 2] = hi;
        *(uint32_t*)&g_aol[row1 + nt * 8 + tig * 2] = lo;
    }
}

// ---------------- launch ----------------------------------------------------
extern "C" void kernel_launch(void* const* d_in, const int* in_sizes, int n_in,
                              void* d_out, int out_size) {
    const float* x           = (const float*)d_in[0];
    const float* timep       = (const float*)d_in[1];
    const float* seq_mask    = (const float*)d_in[2];
    const float* cyclic_mask = (const float*)d_in[3];
    const float* gamma       = (const float*)d_in[4];
    const float* Wt          = (const float*)d_in[5];
    const float* bt          = (const float*)d_in[6];
    const float* Wq          = (const float*)d_in[7];
    const float* Wkv         = (const float*)d_in[8];
    const float* Wo          = (const float*)d_in[9];
    const float* rope_freqs  = (const float*)d_in[10];
    const int*   residue_idx = (const int*)d_in[11];
    const int*   chain_idx   = (const int*)d_in[12];
    float* out = (float*)d_out;

    cudaFuncSetAttribute(mma_gemm_k,
                         cudaFuncAttributeMaxDynamicSharedMemorySize, SM_TOT);
    cudaFuncSetAttribute(attn_mma_k,
                         cudaFuncAttributeMaxDynamicSharedMemorySize, AT_SMEM);

    __half *wh, *woh, *xh, *xl, *aoh, *aol;
    float *qkv;
    cudaGetSymbolAddress((void**)&wh,  g_wh);
    cudaGetSymbolAddress((void**)&woh, g_woh);
    cudaGetSymbolAddress((void**)&xh,  g_xh);
    cudaGetSymbolAddress((void**)&xl,  g_xl);
    cudaGetSymbolAddress((void**)&aoh, g_aoh);
    cudaGetSymbolAddress((void**)&aol, g_aol);
    cudaGetSymbolAddress((void**)&qkv, g_qkv);

    silu_k<<<16, 256>>>(timep);
    zero_counts_k<<<1, 32>>>();
    count_k<<<16, 256>>>(chain_idx, cyclic_mask);
    ss_gemv_k<<<1024, 256>>>(Wt, bt);

    // weight conversions (hi only; B-side residual dropped in 2-product form)
    tohalf_k<<<(1024 * 1024 / 4 + 255) / 256, 256>>>(Wq, wh, 1024 * 1024 / 4);
    tohalf_k<<<(2048 * 1024 / 4 + 255) / 256, 256>>>(Wkv, wh + 1024 * 1024,
                                                     2048 * 1024 / 4);
    tohalf_k<<<(1024 * 1024 / 4 + 255) / 256, 256>>>(Wo, woh, 1024 * 1024 / 4);

    ln_mod_k<<<BB * LL, 256>>>(x, seq_mask, gamma);

    // fused qkv GEMM: [4096,1024] x [3072,1024]^T -> g_qkv [4096,3072]
    mma_gemm_k<<<dim3(24, 32), 256, SM_TOT>>>(xh, xl, wh, qkv,
                                              1024, 3072, nullptr);

    rope_k<<<BB * LL, 128>>>(rope_freqs, residue_idx, chain_idx, cyclic_mask);
    vtrans_k<<<dim3(LL / 64, HH, BB), 256>>>();

    attn_mma_k<<<dim3(LL / 128, HH, BB), 256, AT_SMEM>>>(seq_mask);

    // out = ao @ Wo^T, masked: [4096,1024] x [1024,1024]^T
    mma_gemm_k<<<dim3(8, 32), 256, SM_TOT>>>(aoh, aol, woh, out,
                                             1024, 1024, seq_mask);
}

// round 6
// speedup vs baseline: 7.1723x; 1.5512x over previous
#include <cuda_runtime.h>
#include <cuda_fp16.h>
#include <float.h>
#include <math.h>
#include <stdint.h>

// Problem constants (fixed shapes for this bench)
#define BB   4
#define LL   1024
#define DIMM 1024
#define HH   16
#define DHH  64
#define FF   32      // DH/2 rope frequencies
#define NC   2       // NUM_CHAINS
#define TWO_PI_F 6.2831853071795864769f

// ---------------- scratch (static device globals; no allocation) -----------
__device__ float g_st[BB * DIMM];                 // silu(time)
__device__ float g_ss[BB * 2 * DIMM];             // scale|shift per batch
__device__ float g_counts[BB * NC];               // cyclic counts per chain

// fp16 operands
__device__ __half g_xh[(size_t)BB * LL * DIMM];   // LN+mod output
__device__ __half g_wh[(size_t)3 * DIMM * DIMM];  // [Wq;Wkv]
__device__ __half g_woh[(size_t)DIMM * DIMM];     // Wo
__device__ __half g_aoh[(size_t)BB * LL * DIMM];  // attn out

__device__ float g_qkv[(size_t)BB * LL * 3 * DIMM];      // fused q|k|v GEMM out

// rope'd q/k [B,H,L,DH], transposed v [B,H,DH,L] (all fp16)
__device__ __half g_qh[(size_t)BB * HH * LL * DHH];
__device__ __half g_kh[(size_t)BB * HH * LL * DHH];
__device__ __half g_vth[(size_t)BB * HH * DHH * LL];

// ============================================================================
// PTX helpers (base ISA only)
// ============================================================================
__device__ __forceinline__ uint32_t smem_u32(const void* p) {
    uint32_t a;
    asm("{ .reg .u64 t; cvta.to.shared.u64 t, %1; cvt.u32.u64 %0, t; }"
        : "=r"(a) : "l"(p));
    return a;
}
__device__ __forceinline__ void cpa16(uint32_t dst, const void* src) {
    asm volatile("cp.async.cg.shared.global [%0], [%1], 16;"
                 :: "r"(dst), "l"(src) : "memory");
}
#define CP_COMMIT() asm volatile("cp.async.commit_group;" ::: "memory")
#define CP_WAIT(N)  asm volatile("cp.async.wait_group %0;" :: "n"(N) : "memory")

__device__ __forceinline__ void mma16816(float* d, const uint32_t* a,
                                         const uint32_t* b) {
    asm volatile(
        "mma.sync.aligned.m16n8k16.row.col.f32.f16.f16.f32 "
        "{%0,%1,%2,%3}, {%4,%5,%6,%7}, {%8,%9}, {%0,%1,%2,%3};"
        : "+f"(d[0]), "+f"(d[1]), "+f"(d[2]), "+f"(d[3])
        : "r"(a[0]), "r"(a[1]), "r"(a[2]), "r"(a[3]), "r"(b[0]), "r"(b[1]));
}

__device__ __forceinline__ uint32_t pack2h(float x, float y) {
    __half2 h;
    h.x = __float2half_rn(x);
    h.y = __float2half_rn(y);
    return *(uint32_t*)&h;
}

// ---------------- 1. silu(time) --------------------------------------------
__global__ void silu_k(const float* __restrict__ timep) {
    int i = blockIdx.x * 256 + threadIdx.x;
    if (i < BB * DIMM) {
        float t = timep[i];
        g_st[i] = t / (1.0f + expf(-t));
    }
}

// ---------------- 2. cyclic counts ------------------------------------------
__global__ void zero_counts_k() {
    if (threadIdx.x < BB * NC) g_counts[threadIdx.x] = 0.0f;
}
__global__ void count_k(const int* __restrict__ chain_index,
                        const float* __restrict__ cyclic_mask) {
    int i = blockIdx.x * 256 + threadIdx.x;
    if (i < BB * LL) {
        int b = i / LL;
        atomicAdd(&g_counts[b * NC + chain_index[i]], cyclic_mask[i]);
    }
}

// ---------------- 3. ss = silu(time) @ Wt^T + bt ----------------------------
__global__ void ss_gemv_k(const float* __restrict__ Wt,
                          const float* __restrict__ bt) {
    int warp = (blockIdx.x * blockDim.x + threadIdx.x) >> 5;
    int lane = threadIdx.x & 31;
    if (warp >= BB * 2 * DIMM) return;
    int b = warp / (2 * DIMM);
    int r = warp % (2 * DIMM);
    const float4* w4 = (const float4*)(Wt + (size_t)r * DIMM);
    const float4* s4 = (const float4*)(g_st + b * DIMM);
    float sum = 0.0f;
#pragma unroll
    for (int i = 0; i < 8; i++) {
        float4 w = w4[lane + i * 32];
        float4 s = s4[lane + i * 32];
        sum += w.x * s.x + w.y * s.y + w.z * s.z + w.w * s.w;
    }
#pragma unroll
    for (int o = 16; o; o >>= 1) sum += __shfl_down_sync(0xffffffffu, sum, o);
    if (lane == 0) g_ss[b * 2 * DIMM + r] = sum + bt[r];
}

// ---------------- 4. fp32 -> fp16 ------------------------------------------
__global__ void tohalf_k(const float* __restrict__ src,
                         __half* __restrict__ dst, int n4) {
    int i = blockIdx.x * 256 + threadIdx.x;
    if (i < n4) {
        float4 x = ((const float4*)src)[i];
        ((uint32_t*)dst)[i * 2]     = pack2h(x.x, x.y);
        ((uint32_t*)dst)[i * 2 + 1] = pack2h(x.z, x.w);
    }
}

// ---------------- 5. LayerNorm + modulation (writes fp16) -------------------
__global__ void ln_mod_k(const float* __restrict__ x,
                         const float* __restrict__ seq_mask,
                         const float* __restrict__ gamma) {
    int row = blockIdx.x;          // b*L + l
    int b   = row / LL;
    int tid = threadIdx.x;

    float mval = seq_mask[row];
    float4 xv = ((const float4*)x)[(size_t)row * 256 + tid];
    xv.x *= mval; xv.y *= mval; xv.z *= mval; xv.w *= mval;

    float s = xv.x + xv.y + xv.z + xv.w;
    float q = xv.x * xv.x + xv.y * xv.y + xv.z * xv.z + xv.w * xv.w;

    __shared__ float rs[256];
    __shared__ float rq[256];
    rs[tid] = s; rq[tid] = q;
    __syncthreads();
#pragma unroll
    for (int o = 128; o; o >>= 1) {
        if (tid < o) { rs[tid] += rs[tid + o]; rq[tid] += rq[tid + o]; }
        __syncthreads();
    }
    float mu   = rs[0] * (1.0f / DIMM);
    float var  = rq[0] * (1.0f / DIMM) - mu * mu;
    float rstd = rsqrtf(var + 1e-5f);

    float4 g  = ((const float4*)gamma)[tid];
    float4 sc = ((const float4*)g_ss)[b * 512 + tid];
    float4 sh = ((const float4*)g_ss)[b * 512 + 256 + tid];

    float4 o;
    o.x = (xv.x - mu) * rstd * g.x * (sc.x + 1.0f) + sh.x;
    o.y = (xv.y - mu) * rstd * g.y * (sc.y + 1.0f) + sh.y;
    o.z = (xv.z - mu) * rstd * g.z * (sc.z + 1.0f) + sh.z;
    o.w = (xv.w - mu) * rstd * g.w * (sc.w + 1.0f) + sh.w;

    size_t p = (size_t)row * 512 + tid * 2;
    ((uint32_t*)g_xh)[p]     = pack2h(o.x, o.y);
    ((uint32_t*)g_xh)[p + 1] = pack2h(o.z, o.w);
}

// ---------------- 6. mma.sync fp16 GEMM: C = A @ B^T ------------------------
// Tile 128x128, BK=32, 8 warps (2x4), warptile 64x32, single product.
#define TILE_B   10240                       // bytes per tile (128*40*2)
#define STAGE_B  (2 * TILE_B)                // A,B = 20480 B
#define SM_TOT   (2 * STAGE_B)               // double buffered: 40960 B

__global__ __launch_bounds__(256)
void mma_gemm_k(const __half* __restrict__ Ah,
                const __half* __restrict__ Bh,
                float* __restrict__ C, int K, int ldc,
                const float* __restrict__ rowmask) {
    extern __shared__ __align__(16) char smem[];
    const int tid  = threadIdx.x;
    const int wid  = tid >> 5;
    const int lane = tid & 31;
    const int gid  = lane >> 2;          // 0..7
    const int tig  = lane & 3;           // 0..3
    const int m0 = blockIdx.y * 128;
    const int n0 = blockIdx.x * 128;
    const int wm = wid & 1;              // 0..1  (m warp)
    const int wn = wid >> 1;             // 0..3  (n warp)

    uint32_t sb = smem_u32(smem);

    const int lrow = tid >> 1;
    const int lk   = (tid & 1) * 16;
    const __half* gAh = Ah + (size_t)(m0 + lrow) * K + lk;
    const __half* gBh = Bh + (size_t)(n0 + lrow) * K + lk;
    const uint32_t doff = (uint32_t)lrow * 80 + (uint32_t)lk * 2;

    float acc[4][4][4];
#pragma unroll
    for (int a = 0; a < 4; a++)
#pragma unroll
        for (int b = 0; b < 4; b++)
#pragma unroll
            for (int c = 0; c < 4; c++) acc[a][b][c] = 0.0f;

    const int niter = K >> 5;

    {
        uint32_t base = sb;
        cpa16(base + doff,              gAh);
        cpa16(base + doff + 16,         gAh + 8);
        cpa16(base + TILE_B + doff,      gBh);
        cpa16(base + TILE_B + doff + 16, gBh + 8);
        CP_COMMIT();
    }

    for (int it = 0; it < niter; it++) {
        if (it + 1 < niter) {
            int k0 = (it + 1) << 5;
            uint32_t base = sb + ((it + 1) & 1) * STAGE_B;
            cpa16(base + doff,              gAh + k0);
            cpa16(base + doff + 16,         gAh + k0 + 8);
            cpa16(base + TILE_B + doff,      gBh + k0);
            cpa16(base + TILE_B + doff + 16, gBh + k0 + 8);
            CP_COMMIT();
            CP_WAIT(1);
        } else {
            CP_WAIT(0);
        }
        __syncthreads();

        const char* st = smem + (it & 1) * STAGE_B;
        const char* sAh = st;
        const char* sBh = st + TILE_B;

#pragma unroll
        for (int kk = 0; kk < 32; kk += 16) {
            uint32_t ah[4][4], bh[4][2];
#pragma unroll
            for (int mt = 0; mt < 4; mt++) {
                int r0 = wm * 64 + mt * 16 + gid;
                int ko = (kk + tig * 2) * 2;
                ah[mt][0] = *(const uint32_t*)(sAh + r0 * 80 + ko);
                ah[mt][1] = *(const uint32_t*)(sAh + (r0 + 8) * 80 + ko);
                ah[mt][2] = *(const uint32_t*)(sAh + r0 * 80 + ko + 16);
                ah[mt][3] = *(const uint32_t*)(sAh + (r0 + 8) * 80 + ko + 16);
            }
#pragma unroll
            for (int nt = 0; nt < 4; nt++) {
                int r0 = wn * 32 + nt * 8 + gid;
                int ko = (kk + tig * 2) * 2;
                bh[nt][0] = *(const uint32_t*)(sBh + r0 * 80 + ko);
                bh[nt][1] = *(const uint32_t*)(sBh + r0 * 80 + ko + 16);
            }
#pragma unroll
            for (int mt = 0; mt < 4; mt++)
#pragma unroll
                for (int nt = 0; nt < 4; nt++)
                    mma16816(acc[mt][nt], ah[mt], bh[nt]);
        }
        __syncthreads();
    }

#pragma unroll
    for (int mt = 0; mt < 4; mt++) {
        int m = m0 + wm * 64 + mt * 16 + gid;
        float mk0 = rowmask ? rowmask[m] : 1.0f;
        float mk1 = rowmask ? rowmask[m + 8] : 1.0f;
#pragma unroll
        for (int nt = 0; nt < 4; nt++) {
            int n = n0 + wn * 32 + nt * 8 + tig * 2;
            float2 v0 = make_float2(acc[mt][nt][0] * mk0, acc[mt][nt][1] * mk0);
            float2 v1 = make_float2(acc[mt][nt][2] * mk1, acc[mt][nt][3] * mk1);
            *(float2*)&C[(size_t)m * ldc + n]       = v0;
            *(float2*)&C[(size_t)(m + 8) * ldc + n] = v1;
        }
    }
}

// ---------------- 7. cyclic RoPE -> fp16 q/k [B,H,L,DH] ---------------------
__global__ void rope_k(const float* __restrict__ rope_freqs,
                       const int* __restrict__ residue_index,
                       const int* __restrict__ chain_index,
                       const float* __restrict__ cyclic_mask) {
    int row = blockIdx.x;          // b*L + l
    int b = row / LL, l = row % LL;
    int tid = threadIdx.x;

    __shared__ float cs[FF], sn[FF];
    if (tid < FF) {
        float t  = (float)residue_index[row];
        int   ci = chain_index[row];
        float cm = cyclic_mask[row];
        float a;
        if (cm > 0.0f) {
            float ring = g_counts[b * NC + ci] * cm;
            float rsafe = fmaxf(ring, 1.0f);
            float mk = fmaxf(floorf(rsafe * 0.5f), 1.0f);
            float kf = (float)(tid + 1);
            float keff = (mk == 1.0f) ? 1.0f : (1.0f + fmodf(kf - 1.0f, mk));
            float om = (TWO_PI_F * keff) / rsafe;
            a = om * t;
        } else {
            a = t * rope_freqs[tid] + (float)ci * rope_freqs[0];
        }
        sincosf(a, &sn[tid], &cs[tid]);
    }
    __syncthreads();

    const float2* q2 = (const float2*)(g_qkv + (size_t)row * 3072);
    const float2* k2 = q2 + 512;

#pragma unroll
    for (int i = 0; i < 4; i++) {
        int p = tid + i * 128;       // pair index; h = p/32, f = p%32
        int h = p >> 5, f = p & 31;
        float c = cs[f], s = sn[f];
        float2 q = q2[p];
        float2 k = k2[p];
        float qx = (q.x * c - q.y * s) * 0.125f;
        float qy = (q.y * c + q.x * s) * 0.125f;
        float kx = k.x * c - k.y * s;
        float ky = k.y * c + k.x * s;
        size_t dst = ((size_t)(b * HH + h) * LL + l) * 32 + f;   // 4B units
        ((uint32_t*)g_qh)[dst] = pack2h(qx, qy);
        ((uint32_t*)g_kh)[dst] = pack2h(kx, ky);
    }
}

// ---------------- 8. V transpose: qkv v-section -> fp16 [B,H,DH,L] ----------
__global__ void vtrans_k() {
    __shared__ float ts[64][65];
    int lt = blockIdx.x;           // l tile (64)
    int h  = blockIdx.y;
    int b  = blockIdx.z;
    int tid = threadIdx.x;

    int l  = tid >> 2;             // 0..63
    int d0 = (tid & 3) * 16;       // 0,16,32,48
    const float* src = g_qkv + ((size_t)(b * LL + lt * 64 + l)) * 3072 +
                       2048 + h * 64 + d0;
#pragma unroll
    for (int j = 0; j < 4; j++) {
        float4 v = *(const float4*)(src + j * 4);
        ts[d0 + j * 4 + 0][l] = v.x;
        ts[d0 + j * 4 + 1][l] = v.y;
        ts[d0 + j * 4 + 2][l] = v.z;
        ts[d0 + j * 4 + 3][l] = v.w;
    }
    __syncthreads();

    int d  = tid >> 2;
    int l0 = (tid & 3) * 16;
    uint32_t hbuf[8];
#pragma unroll
    for (int j = 0; j < 8; j++)
        hbuf[j] = pack2h(ts[d][l0 + j * 2], ts[d][l0 + j * 2 + 1]);
    size_t dst = ((size_t)(b * HH + h) * DHH + d) * LL + lt * 64 + l0;
    *(uint4*)&g_vth[dst]     = *(uint4*)&hbuf[0];
    *(uint4*)&g_vth[dst + 8] = *(uint4*)&hbuf[4];
}

// ---------------- 9. flash attention, mma.sync fp16 (1 product) -------------
// CTA: 128 queries (8 warps x 16 rows), key tiles of 64, double-buffered smem.
#define AT_KSTR  144                       // bytes per row (64 fp16 + pad)
#define AT_TILE  (64 * AT_KSTR)            // 9216 B
#define AT_STAGE (2 * AT_TILE)             // K,V = 18432 B
#define AT_SMEM  (2 * AT_STAGE)            // 36864 B

__global__ __launch_bounds__(256)
void attn_mma_k(const float* __restrict__ seq_mask) {
    extern __shared__ __align__(16) char smem[];
    const int tid  = threadIdx.x;
    const int wid  = tid >> 5;
    const int lane = tid & 31;
    const int gid  = lane >> 2;
    const int tig  = lane & 3;
    const int b  = blockIdx.z;
    const int h  = blockIdx.y;
    const int qt = blockIdx.x;
    const size_t bh = (size_t)(b * HH + h);

    uint32_t sb = smem_u32(smem);

    // load Q fragments (16 rows per warp)
    const int qr = qt * 128 + wid * 16;
    uint32_t qh[4][4];
#pragma unroll
    for (int kc = 0; kc < 4; kc++) {
        size_t r0 = (bh * LL + qr + gid) * 64 + kc * 16 + tig * 2;
        size_t r1 = r0 + 8 * 64;
        qh[kc][0] = *(const uint32_t*)&g_qh[r0];
        qh[kc][1] = *(const uint32_t*)&g_qh[r1];
        qh[kc][2] = *(const uint32_t*)&g_qh[r0 + 8];
        qh[kc][3] = *(const uint32_t*)&g_qh[r1 + 8];
    }

    float O[8][4];
#pragma unroll
    for (int nt = 0; nt < 8; nt++)
#pragma unroll
        for (int c = 0; c < 4; c++) O[nt][c] = 0.0f;
    float m0 = -FLT_MAX, m1 = -FLT_MAX, l0s = 0.0f, l1s = 0.0f;

    const int cr = tid >> 2;            // row 0..63
    const int cc = (tid * 2) & 7;       // chunk pair
    const __half* Kh_g = g_kh + (bh * LL) * 64;
    const __half* Vh_g = g_vth + (bh * DHH) * LL;

#define AT_LOAD(stage, kt)                                                    \
    {                                                                         \
        uint32_t base = sb + (stage) * AT_STAGE;                              \
        uint32_t so = (uint32_t)cr * AT_KSTR + (uint32_t)cc * 16;             \
        const __half* k_src = Kh_g + ((size_t)(kt) * 64 + cr) * 64 + cc * 8;  \
        const __half* v_src = Vh_g + (size_t)cr * LL + (kt) * 64 + cc * 8;    \
        cpa16(base + so, k_src);                                              \
        cpa16(base + so + 16, k_src + 8);                                     \
        cpa16(base + AT_TILE + so, v_src);                                    \
        cpa16(base + AT_TILE + so + 16, v_src + 8);                           \
        CP_COMMIT();                                                          \
    }

    AT_LOAD(0, 0);

    for (int kt = 0; kt < 16; kt++) {
        if (kt + 1 < 16) {
            AT_LOAD((kt + 1) & 1, kt + 1);
            CP_WAIT(1);
        } else {
            CP_WAIT(0);
        }
        __syncthreads();

        const char* st  = smem + (kt & 1) * AT_STAGE;
        const char* sKh = st;
        const char* sVh = st + AT_TILE;

        // ---- S = Q K^T ----
        float S[8][4];
#pragma unroll
        for (int nt = 0; nt < 8; nt++)
#pragma unroll
            for (int c = 0; c < 4; c++) S[nt][c] = 0.0f;

#pragma unroll
        for (int kc = 0; kc < 4; kc++) {
            int ko = (kc * 16 + tig * 2) * 2;
#pragma unroll
            for (int nt = 0; nt < 8; nt++) {
                int roff = (nt * 8 + gid) * AT_KSTR + ko;
                uint32_t bhv[2];
                bhv[0] = *(const uint32_t*)(sKh + roff);
                bhv[1] = *(const uint32_t*)(sKh + roff + 16);
                mma16816(S[nt], qh[kc], bhv);
            }
        }

        // ---- mask ----
        const float* mrow = seq_mask + b * LL + kt * 64;
#pragma unroll
        for (int nt = 0; nt < 8; nt++) {
            float mk0 = __ldg(mrow + nt * 8 + tig * 2);
            float mk1 = __ldg(mrow + nt * 8 + tig * 2 + 1);
            if (mk0 <= 0.0f) { S[nt][0] = -1e30f; S[nt][2] = -1e30f; }
            if (mk1 <= 0.0f) { S[nt][1] = -1e30f; S[nt][3] = -1e30f; }
        }

        // ---- online softmax ----
        float t0 = -FLT_MAX, t1 = -FLT_MAX;
#pragma unroll
        for (int nt = 0; nt < 8; nt++) {
            t0 = fmaxf(t0, fmaxf(S[nt][0], S[nt][1]));
            t1 = fmaxf(t1, fmaxf(S[nt][2], S[nt][3]));
        }
        t0 = fmaxf(t0, __shfl_xor_sync(0xffffffffu, t0, 1));
        t0 = fmaxf(t0, __shfl_xor_sync(0xffffffffu, t0, 2));
        t1 = fmaxf(t1, __shfl_xor_sync(0xffffffffu, t1, 1));
        t1 = fmaxf(t1, __shfl_xor_sync(0xffffffffu, t1, 2));

        float mn0 = fmaxf(m0, t0);
        float mn1 = fmaxf(m1, t1);
        float cr0 = __expf(m0 - mn0);
        float cr1 = __expf(m1 - mn1);
        m0 = mn0; m1 = mn1;

        float ps0 = 0.0f, ps1 = 0.0f;
#pragma unroll
        for (int nt = 0; nt < 8; nt++) {
            S[nt][0] = __expf(S[nt][0] - mn0);
            S[nt][1] = __expf(S[nt][1] - mn0);
            S[nt][2] = __expf(S[nt][2] - mn1);
            S[nt][3] = __expf(S[nt][3] - mn1);
            ps0 += S[nt][0] + S[nt][1];
            ps1 += S[nt][2] + S[nt][3];
        }
        ps0 += __shfl_xor_sync(0xffffffffu, ps0, 1);
        ps0 += __shfl_xor_sync(0xffffffffu, ps0, 2);
        ps1 += __shfl_xor_sync(0xffffffffu, ps1, 1);
        ps1 += __shfl_xor_sync(0xffffffffu, ps1, 2);
        l0s = l0s * cr0 + ps0;
        l1s = l1s * cr1 + ps1;

#pragma unroll
        for (int nt = 0; nt < 8; nt++) {
            O[nt][0] *= cr0; O[nt][1] *= cr0;
            O[nt][2] *= cr1; O[nt][3] *= cr1;
        }

        // ---- O += P V ----
#pragma unroll
        for (int kc = 0; kc < 4; kc++) {
            uint32_t pa[4];
            pa[0] = pack2h(S[2 * kc][0],     S[2 * kc][1]);
            pa[1] = pack2h(S[2 * kc][2],     S[2 * kc][3]);
            pa[2] = pack2h(S[2 * kc + 1][0], S[2 * kc + 1][1]);
            pa[3] = pack2h(S[2 * kc + 1][2], S[2 * kc + 1][3]);
            int ko = (kc * 16 + tig * 2) * 2;
#pragma unroll
            for (int nt = 0; nt < 8; nt++) {
                int roff = (nt * 8 + gid) * AT_KSTR + ko;
                uint32_t bhv[2];
                bhv[0] = *(const uint32_t*)(sVh + roff);
                bhv[1] = *(const uint32_t*)(sVh + roff + 16);
                mma16816(O[nt], pa, bhv);
            }
        }
        __syncthreads();
    }

    // ---- epilogue: O/l -> fp16 at [b, l, h*64+dh] ----
    float inv0 = 1.0f / l0s;
    float inv1 = 1.0f / l1s;
    size_t row0 = (size_t)(b * LL + qr + gid) * 1024 + h * 64;
    size_t row1 = row0 + 8 * 1024;
#pragma unroll
    for (int nt = 0; nt < 8; nt++) {
        *(uint32_t*)&g_aoh[row0 + nt * 8 + tig * 2] =
            pack2h(O[nt][0] * inv0, O[nt][1] * inv0);
        *(uint32_t*)&g_aoh[row1 + nt * 8 + tig * 2] =
            pack2h(O[nt][2] * inv1, O[nt][3] * inv1);
    }
}

// ---------------- launch ----------------------------------------------------
extern "C" void kernel_launch(void* const* d_in, const int* in_sizes, int n_in,
                              void* d_out, int out_size) {
    const float* x           = (const float*)d_in[0];
    const float* timep       = (const float*)d_in[1];
    const float* seq_mask    = (const float*)d_in[2];
    const float* cyclic_mask = (const float*)d_in[3];
    const float* gamma       = (const float*)d_in[4];
    const float* Wt          = (const float*)d_in[5];
    const float* bt          = (const float*)d_in[6];
    const float* Wq          = (const float*)d_in[7];
    const float* Wkv         = (const float*)d_in[8];
    const float* Wo          = (const float*)d_in[9];
    const float* rope_freqs  = (const float*)d_in[10];
    const int*   residue_idx = (const int*)d_in[11];
    const int*   chain_idx   = (const int*)d_in[12];
    float* out = (float*)d_out;

    cudaFuncSetAttribute(mma_gemm_k,
                         cudaFuncAttributeMaxDynamicSharedMemorySize, SM_TOT);
    cudaFuncSetAttribute(attn_mma_k,
                         cudaFuncAttributeMaxDynamicSharedMemorySize, AT_SMEM);

    __half *wh, *woh, *xh, *aoh;
    float *qkv;
    cudaGetSymbolAddress((void**)&wh,  g_wh);
    cudaGetSymbolAddress((void**)&woh, g_woh);
    cudaGetSymbolAddress((void**)&xh,  g_xh);
    cudaGetSymbolAddress((void**)&aoh, g_aoh);
    cudaGetSymbolAddress((void**)&qkv, g_qkv);

    silu_k<<<16, 256>>>(timep);
    zero_counts_k<<<1, 32>>>();
    count_k<<<16, 256>>>(chain_idx, cyclic_mask);
    ss_gemv_k<<<1024, 256>>>(Wt, bt);

    tohalf_k<<<(1024 * 1024 / 4 + 255) / 256, 256>>>(Wq, wh, 1024 * 1024 / 4);
    tohalf_k<<<(2048 * 1024 / 4 + 255) / 256, 256>>>(Wkv, wh + 1024 * 1024,
                                                     2048 * 1024 / 4);
    tohalf_k<<<(1024 * 1024 / 4 + 255) / 256, 256>>>(Wo, woh, 1024 * 1024 / 4);

    ln_mod_k<<<BB * LL, 256>>>(x, seq_mask, gamma);

    // fused qkv GEMM: [4096,1024] x [3072,1024]^T -> g_qkv [4096,3072]
    mma_gemm_k<<<dim3(24, 32), 256, SM_TOT>>>(xh, wh, qkv, 1024, 3072, nullptr);

    rope_k<<<BB * LL, 128>>>(rope_freqs, residue_idx, chain_idx, cyclic_mask);
    vtrans_k<<<dim3(LL / 64, HH, BB), 256>>>();

    attn_mma_k<<<dim3(LL / 128, HH, BB), 256, AT_SMEM>>>(seq_mask);

    // out = ao @ Wo^T, masked: [4096,1024] x [1024,1024]^T
    mma_gemm_k<<<dim3(8, 32), 256, SM_TOT>>>(aoh, woh, out, 1024, 1024, seq_mask);
}